// round 1
// baseline (speedup 1.0000x reference)
#include <cuda_runtime.h>

#define BB 2
#define SS 2048
#define DD 768
#define HH 12
#define DKK 64
#define MM (BB*SS)

// Scratch (no allocation allowed): head-split Q/K/V [B,H,S,DK] and attended [B*S,D]
__device__ float g_q[BB*HH*SS*DKK];
__device__ float g_k[BB*HH*SS*DKK];
__device__ float g_v[BB*HH*SS*DKK];
__device__ float g_att[MM*DD];

// ---------------------------------------------------------------------------
// QKV projection: out[m,n] = sum_k x[m,k] * W[n,k]   (y = x W^T)
// grid (Mtiles=64, Ntiles=12, 3), block 256, 64x64 tile, BK=16, 4x4 per thread
// Writes head-split layout; q scaled by 1/sqrt(DK).
// ---------------------------------------------------------------------------
__global__ __launch_bounds__(256) void proj_kernel(
    const float* __restrict__ xq, const float* __restrict__ xk, const float* __restrict__ xv,
    const float* __restrict__ wq, const float* __restrict__ wk, const float* __restrict__ wv)
{
    __shared__ float As[16][68];   // [k][m], padded
    __shared__ float Bs[16][68];   // [k][n], padded

    const int z = blockIdx.z;
    const float* __restrict__ x = (z == 0) ? xq : (z == 1) ? xk : xv;
    const float* __restrict__ w = (z == 0) ? wq : (z == 1) ? wk : wv;
    float* __restrict__ out      = (z == 0) ? g_q : (z == 1) ? g_k : g_v;
    const float scale = (z == 0) ? 0.125f : 1.0f;   // 1/sqrt(64)

    const int m0 = blockIdx.x * 64;
    const int n0 = blockIdx.y * 64;
    const int tid = threadIdx.x;
    const int ty = tid >> 4, tx = tid & 15;
    const int lr  = tid >> 2;   // 0..63 tile row for loads
    const int lc4 = tid & 3;    // float4 index along k

    float acc[4][4] = {};

    for (int k0 = 0; k0 < DD; k0 += 16) {
        float4 av = *(const float4*)&x[(m0 + lr) * DD + k0 + lc4 * 4];
        float4 bv = *(const float4*)&w[(n0 + lr) * DD + k0 + lc4 * 4];
        __syncthreads();
        As[lc4*4+0][lr] = av.x; As[lc4*4+1][lr] = av.y;
        As[lc4*4+2][lr] = av.z; As[lc4*4+3][lr] = av.w;
        Bs[lc4*4+0][lr] = bv.x; Bs[lc4*4+1][lr] = bv.y;
        Bs[lc4*4+2][lr] = bv.z; Bs[lc4*4+3][lr] = bv.w;
        __syncthreads();
        #pragma unroll
        for (int kk = 0; kk < 16; kk++) {
            float4 a = *(const float4*)&As[kk][ty * 4];
            float4 b = *(const float4*)&Bs[kk][tx * 4];
            acc[0][0] += a.x*b.x; acc[0][1] += a.x*b.y; acc[0][2] += a.x*b.z; acc[0][3] += a.x*b.w;
            acc[1][0] += a.y*b.x; acc[1][1] += a.y*b.y; acc[1][2] += a.y*b.z; acc[1][3] += a.y*b.w;
            acc[2][0] += a.z*b.x; acc[2][1] += a.z*b.y; acc[2][2] += a.z*b.z; acc[2][3] += a.z*b.w;
            acc[3][0] += a.w*b.x; acc[3][1] += a.w*b.y; acc[3][2] += a.w*b.z; acc[3][3] += a.w*b.w;
        }
    }

    // head-split write: n tile == one head exactly (64 == DK)
    const int h = blockIdx.y;
    #pragma unroll
    for (int r = 0; r < 4; r++) {
        const int m = m0 + ty * 4 + r;
        const int b = m >> 11;          // /S
        const int s = m & (SS - 1);
        float4 v = make_float4(acc[r][0]*scale, acc[r][1]*scale, acc[r][2]*scale, acc[r][3]*scale);
        *(float4*)&out[(((size_t)(b * HH + h) * SS) + s) * DKK + tx * 4] = v;
    }
}

// ---------------------------------------------------------------------------
// Flash attention (causal), fp32. grid (32 qtiles, 24 bh), block 256.
// 64x64 score tiles, online softmax, 4x4 register tiles per thread.
// ---------------------------------------------------------------------------
#define ATTN_SMEM_FLOATS (4*64*68 + 3*64)

__global__ __launch_bounds__(256) void attn_kernel()
{
    extern __shared__ float sm[];
    float* Qt   = sm;              // [d][i], stride 68
    float* Kt   = sm + 64*68;      // [d][j], stride 68
    float* Vs   = sm + 2*64*68;    // [j][d], stride 68
    float* Ps   = sm + 3*64*68;    // [i][j], stride 68
    float* rowm = sm + 4*64*68;
    float* rowl = rowm + 64;
    float* rowa = rowl + 64;

    const int qt = blockIdx.x;
    const int bh = blockIdx.y;
    const float* __restrict__ Qg = g_q + ((size_t)bh * SS + qt * 64) * DKK;
    const float* __restrict__ Kg = g_k + (size_t)bh * SS * DKK;
    const float* __restrict__ Vg = g_v + (size_t)bh * SS * DKK;

    const int tid = threadIdx.x;
    const int ty = tid >> 4, tx = tid & 15;

    // load Q tile transposed (scale already folded in)
    for (int u = tid; u < 64 * 16; u += 256) {
        int r = u >> 4, c4 = u & 15;
        float4 v = *(const float4*)&Qg[r * 64 + c4 * 4];
        Qt[(c4*4+0)*68 + r] = v.x; Qt[(c4*4+1)*68 + r] = v.y;
        Qt[(c4*4+2)*68 + r] = v.z; Qt[(c4*4+3)*68 + r] = v.w;
    }
    if (tid < 64) { rowm[tid] = -1e30f; rowl[tid] = 0.0f; }

    float o[4][4] = {};
    __syncthreads();

    for (int kt = 0; kt <= qt; kt++) {
        const float* __restrict__ Kgt = Kg + (size_t)kt * 64 * 64;
        const float* __restrict__ Vgt = Vg + (size_t)kt * 64 * 64;
        for (int u = tid; u < 64 * 16; u += 256) {
            int r = u >> 4, c4 = u & 15;
            float4 kv = *(const float4*)&Kgt[r * 64 + c4 * 4];
            Kt[(c4*4+0)*68 + r] = kv.x; Kt[(c4*4+1)*68 + r] = kv.y;
            Kt[(c4*4+2)*68 + r] = kv.z; Kt[(c4*4+3)*68 + r] = kv.w;
            *(float4*)&Vs[r*68 + c4*4] = *(const float4*)&Vgt[r * 64 + c4 * 4];
        }
        __syncthreads();

        // scores S = Q K^T
        float acc[4][4] = {};
        #pragma unroll 16
        for (int d = 0; d < 64; d++) {
            float4 q = *(const float4*)&Qt[d*68 + ty*4];
            float4 k = *(const float4*)&Kt[d*68 + tx*4];
            acc[0][0] += q.x*k.x; acc[0][1] += q.x*k.y; acc[0][2] += q.x*k.z; acc[0][3] += q.x*k.w;
            acc[1][0] += q.y*k.x; acc[1][1] += q.y*k.y; acc[1][2] += q.y*k.z; acc[1][3] += q.y*k.w;
            acc[2][0] += q.z*k.x; acc[2][1] += q.z*k.y; acc[2][2] += q.z*k.z; acc[2][3] += q.z*k.w;
            acc[3][0] += q.w*k.x; acc[3][1] += q.w*k.y; acc[3][2] += q.w*k.z; acc[3][3] += q.w*k.w;
        }

        // causal mask only on the diagonal tile
        if (kt == qt) {
            #pragma unroll
            for (int r = 0; r < 4; r++)
                #pragma unroll
                for (int c = 0; c < 4; c++)
                    if (tx*4 + c > ty*4 + r) acc[r][c] = -1e30f;
        }

        #pragma unroll
        for (int r = 0; r < 4; r++)
            *(float4*)&Ps[(ty*4+r)*68 + tx*4] =
                make_float4(acc[r][0], acc[r][1], acc[r][2], acc[r][3]);
        __syncthreads();

        // online softmax stats: 4 threads per row
        {
            const int row = tid >> 2, part = tid & 3;
            float* pr = &Ps[row*68 + part*16];
            float mx = -1e30f;
            #pragma unroll
            for (int j = 0; j < 16; j++) mx = fmaxf(mx, pr[j]);
            mx = fmaxf(mx, __shfl_xor_sync(0xffffffffu, mx, 1));
            mx = fmaxf(mx, __shfl_xor_sync(0xffffffffu, mx, 2));
            const float mold = rowm[row];
            const float mnew = fmaxf(mold, mx);
            float sum = 0.0f;
            #pragma unroll
            for (int j = 0; j < 16; j++) {
                float p = __expf(pr[j] - mnew);
                pr[j] = p;
                sum += p;
            }
            sum += __shfl_xor_sync(0xffffffffu, sum, 1);
            sum += __shfl_xor_sync(0xffffffffu, sum, 2);
            if (part == 0) {
                float alpha = __expf(mold - mnew);
                rowa[row] = alpha;
                rowl[row] = rowl[row] * alpha + sum;
                rowm[row] = mnew;
            }
        }
        __syncthreads();

        // rescale accumulator and add P @ V
        {
            float a0 = rowa[ty*4+0], a1 = rowa[ty*4+1], a2 = rowa[ty*4+2], a3 = rowa[ty*4+3];
            #pragma unroll
            for (int c = 0; c < 4; c++) { o[0][c]*=a0; o[1][c]*=a1; o[2][c]*=a2; o[3][c]*=a3; }
            #pragma unroll
            for (int j4 = 0; j4 < 16; j4++) {
                float4 v0 = *(const float4*)&Vs[(j4*4+0)*68 + tx*4];
                float4 v1 = *(const float4*)&Vs[(j4*4+1)*68 + tx*4];
                float4 v2 = *(const float4*)&Vs[(j4*4+2)*68 + tx*4];
                float4 v3 = *(const float4*)&Vs[(j4*4+3)*68 + tx*4];
                #pragma unroll
                for (int r = 0; r < 4; r++) {
                    float4 p = *(const float4*)&Ps[(ty*4+r)*68 + j4*4];
                    o[r][0] += p.x*v0.x; o[r][1] += p.x*v0.y; o[r][2] += p.x*v0.z; o[r][3] += p.x*v0.w;
                    o[r][0] += p.y*v1.x; o[r][1] += p.y*v1.y; o[r][2] += p.y*v1.z; o[r][3] += p.y*v1.w;
                    o[r][0] += p.z*v2.x; o[r][1] += p.z*v2.y; o[r][2] += p.z*v2.z; o[r][3] += p.z*v2.w;
                    o[r][0] += p.w*v3.x; o[r][1] += p.w*v3.y; o[r][2] += p.w*v3.z; o[r][3] += p.w*v3.w;
                }
            }
        }
        __syncthreads();
    }

    // epilogue: normalize and write attended in [B*S, D] layout
    const int b = bh / HH, h = bh - b * HH;
    #pragma unroll
    for (int r = 0; r < 4; r++) {
        const int sg = qt * 64 + ty * 4 + r;
        const float inv = 1.0f / rowl[ty*4+r];
        *(float4*)&g_att[((size_t)(b * SS + sg)) * DD + h * 64 + tx * 4] =
            make_float4(o[r][0]*inv, o[r][1]*inv, o[r][2]*inv, o[r][3]*inv);
    }
}

// ---------------------------------------------------------------------------
// Output projection: out[m,n] = sum_k att[m,k] * Wo[n,k] + bo[n]
// ---------------------------------------------------------------------------
__global__ __launch_bounds__(256) void outproj_kernel(
    const float* __restrict__ wo, const float* __restrict__ bo, float* __restrict__ out)
{
    __shared__ float As[16][68];
    __shared__ float Bs[16][68];

    const int m0 = blockIdx.x * 64;
    const int n0 = blockIdx.y * 64;
    const int tid = threadIdx.x;
    const int ty = tid >> 4, tx = tid & 15;
    const int lr  = tid >> 2;
    const int lc4 = tid & 3;

    float acc[4][4] = {};

    for (int k0 = 0; k0 < DD; k0 += 16) {
        float4 av = *(const float4*)&g_att[(size_t)(m0 + lr) * DD + k0 + lc4 * 4];
        float4 bv = *(const float4*)&wo[(n0 + lr) * DD + k0 + lc4 * 4];
        __syncthreads();
        As[lc4*4+0][lr] = av.x; As[lc4*4+1][lr] = av.y;
        As[lc4*4+2][lr] = av.z; As[lc4*4+3][lr] = av.w;
        Bs[lc4*4+0][lr] = bv.x; Bs[lc4*4+1][lr] = bv.y;
        Bs[lc4*4+2][lr] = bv.z; Bs[lc4*4+3][lr] = bv.w;
        __syncthreads();
        #pragma unroll
        for (int kk = 0; kk < 16; kk++) {
            float4 a = *(const float4*)&As[kk][ty * 4];
            float4 b = *(const float4*)&Bs[kk][tx * 4];
            acc[0][0] += a.x*b.x; acc[0][1] += a.x*b.y; acc[0][2] += a.x*b.z; acc[0][3] += a.x*b.w;
            acc[1][0] += a.y*b.x; acc[1][1] += a.y*b.y; acc[1][2] += a.y*b.z; acc[1][3] += a.y*b.w;
            acc[2][0] += a.z*b.x; acc[2][1] += a.z*b.y; acc[2][2] += a.z*b.z; acc[2][3] += a.z*b.w;
            acc[3][0] += a.w*b.x; acc[3][1] += a.w*b.y; acc[3][2] += a.w*b.z; acc[3][3] += a.w*b.w;
        }
    }

    float4 bias = *(const float4*)&bo[n0 + tx * 4];
    #pragma unroll
    for (int r = 0; r < 4; r++) {
        const int m = m0 + ty * 4 + r;
        *(float4*)&out[(size_t)m * DD + n0 + tx * 4] =
            make_float4(acc[r][0]+bias.x, acc[r][1]+bias.y, acc[r][2]+bias.z, acc[r][3]+bias.w);
    }
}

// ---------------------------------------------------------------------------
extern "C" void kernel_launch(void* const* d_in, const int* in_sizes, int n_in,
                              void* d_out, int out_size)
{
    const float* query = (const float*)d_in[0];
    const float* key   = (const float*)d_in[1];
    const float* value = (const float*)d_in[2];
    // d_in[3] = mask (fixed causal triu, handled analytically)
    const float* wq = (const float*)d_in[4];
    const float* wk = (const float*)d_in[5];
    const float* wv = (const float*)d_in[6];
    const float* wo = (const float*)d_in[7];
    const float* bo = (const float*)d_in[8];
    float* out = (float*)d_out;

    const int attn_smem = ATTN_SMEM_FLOATS * (int)sizeof(float);
    cudaFuncSetAttribute(attn_kernel, cudaFuncAttributeMaxDynamicSharedMemorySize, attn_smem);

    proj_kernel<<<dim3(MM/64, DD/64, 3), 256>>>(query, key, value, wq, wk, wv);
    attn_kernel<<<dim3(SS/64, BB*HH), 256, attn_smem>>>();
    outproj_kernel<<<dim3(MM/64, DD/64), 256>>>(wo, bo, out);
}

// round 3
// speedup vs baseline: 1.3298x; 1.3298x over previous
#include <cuda_runtime.h>
#include <cuda_bf16.h>

#define BB 2
#define SS 2048
#define DD 768
#define HH 12
#define DKK 64
#define MM (BB*SS)
#define NCHUNK 12            /* 768 / 64 */

// Scratch: head-split Q/K/V [B,H,S,DK] and attended [B*S,D]
__device__ float g_q[BB*HH*SS*DKK];
__device__ float g_k[BB*HH*SS*DKK];
__device__ float g_v[BB*HH*SS*DKK];
__device__ float g_att[MM*DD];

// ===========================================================================
// Warp-MMA helpers (sm_80-baseline PTX only — no arch-'a' features)
// ===========================================================================
__device__ __forceinline__ unsigned smem_u32(const void* p) {
    unsigned a;
    asm("{ .reg .u64 t; cvta.to.shared.u64 t, %1; cvt.u32.u64 %0, t; }"
        : "=r"(a) : "l"(p));
    return a;
}
__device__ __forceinline__ void ldm_x4(unsigned r[4], unsigned addr) {
    asm volatile("ldmatrix.sync.aligned.m8n8.x4.shared.b16 {%0,%1,%2,%3}, [%4];"
                 : "=r"(r[0]), "=r"(r[1]), "=r"(r[2]), "=r"(r[3]) : "r"(addr));
}
__device__ __forceinline__ void mma_bf16(float d[4], const unsigned a[4],
                                         unsigned b0, unsigned b1) {
    asm volatile(
        "mma.sync.aligned.m16n8k16.row.col.f32.bf16.bf16.f32 "
        "{%0,%1,%2,%3}, {%4,%5,%6,%7}, {%8,%9}, {%0,%1,%2,%3};"
        : "+f"(d[0]), "+f"(d[1]), "+f"(d[2]), "+f"(d[3])
        : "r"(a[0]), "r"(a[1]), "r"(a[2]), "r"(a[3]), "r"(b0), "r"(b1));
}
__device__ __forceinline__ unsigned pk(__nv_bfloat16 a, __nv_bfloat16 b) {
    return (unsigned)__bfloat16_as_ushort(a) | ((unsigned)__bfloat16_as_ushort(b) << 16);
}

// split one fp32 octet into hi/lo bf16 octets (packed)
__device__ __forceinline__ void cvt8(float4 v0, float4 v1, uint4& H, uint4& L) {
    float f[8] = {v0.x, v0.y, v0.z, v0.w, v1.x, v1.y, v1.z, v1.w};
    unsigned h[4], l[4];
    #pragma unroll
    for (int i = 0; i < 4; i++) {
        float a = f[2*i], b = f[2*i+1];
        __nv_bfloat16 ha = __float2bfloat16_rn(a);
        __nv_bfloat16 hb = __float2bfloat16_rn(b);
        __nv_bfloat16 la = __float2bfloat16_rn(a - __bfloat162float(ha));
        __nv_bfloat16 lb = __float2bfloat16_rn(b - __bfloat162float(hb));
        h[i] = pk(ha, hb);
        l[i] = pk(la, lb);
    }
    H = make_uint4(h[0], h[1], h[2], h[3]);
    L = make_uint4(l[0], l[1], l[2], l[3]);
}

// Load a [128 x 64] fp32 tile, split to hi/lo bf16, store swizzled to smem.
// smem row = 64 bf16 = 128B = 8 chunks of 16B; phys chunk = chunk ^ (row & 7).
__device__ __forceinline__ void load_tile(const float* __restrict__ src,
                                          int row0, int k0, char* hb, char* lb) {
    const int tid = threadIdx.x;
    #pragma unroll
    for (int i = 0; i < 4; i++) {
        int u = i * 256 + tid;      // 0..1023
        int r = u >> 3;             // 0..127
        int o = u & 7;              // octet
        const float* p = src + (size_t)(row0 + r) * DD + k0 + o * 8;
        float4 v0 = *(const float4*)p;
        float4 v1 = *(const float4*)(p + 4);
        uint4 H, L;
        cvt8(v0, v1, H, L);
        int off = r * 128 + ((o ^ (r & 7)) * 16);
        *(uint4*)(hb + off) = H;
        *(uint4*)(lb + off) = L;
    }
}

// ===========================================================================
// Split-bf16 GEMM core: D[128x128] = X[128rows x 768] * W[128rows x 768]^T
// 8 warps as 4(m) x 2(n); each warp computes 32 x 64 via m16n8k16 mma.
// 3 products: XhWh + XhWl + XlWh, fp32 accumulate -> ~1e-6 rel err.
// ===========================================================================
#define GEMM_SMEM 65536

__device__ __forceinline__ void gemm_core(const float* __restrict__ X,
                                          const float* __restrict__ W,
                                          int m0, int n0, char* smem,
                                          float d[2][8][4]) {
    const int tid = threadIdx.x, lane = tid & 31, wid = tid >> 5;
    const int wm0 = (wid >> 1) * 32;
    const int wn0 = (wid & 1) * 64;
    char* sXh = smem;
    char* sXl = smem + 16384;
    char* sWh = smem + 32768;
    char* sWl = smem + 49152;
    const unsigned uXh = smem_u32(sXh), uXl = smem_u32(sXl);
    const unsigned uWh = smem_u32(sWh), uWl = smem_u32(sWl);

    const int l15 = lane & 15, lhi = lane >> 4, l7 = lane & 7;

    #pragma unroll
    for (int mi = 0; mi < 2; mi++)
        #pragma unroll
        for (int ni = 0; ni < 8; ni++)
            #pragma unroll
            for (int k = 0; k < 4; k++) d[mi][ni][k] = 0.0f;

    for (int c = 0; c < NCHUNK; c++) {
        if (c) __syncthreads();           // all warps done with previous chunk
        load_tile(X, m0, c * 64, sXh, sXl);
        load_tile(W, n0, c * 64, sWh, sWl);
        __syncthreads();

        #pragma unroll
        for (int p = 0; p < 3; p++) {
            const unsigned Ab = (p == 2) ? uXl : uXh;
            const unsigned Bb = (p == 1) ? uWl : uWh;
            #pragma unroll
            for (int ks = 0; ks < 4; ks++) {
                const int sw = (((2 * ks + lhi) ^ l7) * 16);
                unsigned a[2][4], bb[4][4];
                ldm_x4(a[0], Ab + (wm0      + l15) * 128 + sw);
                ldm_x4(a[1], Ab + (wm0 + 16 + l15) * 128 + sw);
                #pragma unroll
                for (int np = 0; np < 4; np++)
                    ldm_x4(bb[np], Bb + (wn0 + np * 16 + l15) * 128 + sw);
                #pragma unroll
                for (int mi = 0; mi < 2; mi++)
                    #pragma unroll
                    for (int np = 0; np < 4; np++) {
                        mma_bf16(d[mi][2*np],     a[mi], bb[np][0], bb[np][2]);
                        mma_bf16(d[mi][2*np + 1], a[mi], bb[np][1], bb[np][3]);
                    }
            }
        }
    }
}

// ===========================================================================
// QKV projection. grid (32, 6, 3), block 256. Head-split output, q scaled.
// ===========================================================================
__global__ __launch_bounds__(256, 2) void tc_proj_kernel(
    const float* __restrict__ xq, const float* __restrict__ xk, const float* __restrict__ xv,
    const float* __restrict__ wq, const float* __restrict__ wk, const float* __restrict__ wv)
{
    extern __shared__ char smem[];
    const int z = blockIdx.z;
    const float* __restrict__ x = (z == 0) ? xq : (z == 1) ? xk : xv;
    const float* __restrict__ w = (z == 0) ? wq : (z == 1) ? wk : wv;
    float* __restrict__ outp    = (z == 0) ? g_q : (z == 1) ? g_k : g_v;
    const float scale = (z == 0) ? 0.125f : 1.0f;

    const int m0 = blockIdx.x * 128;
    const int n0 = blockIdx.y * 128;

    float d[2][8][4];
    gemm_core(x, w, m0, n0, smem, d);

    const int lane = threadIdx.x & 31, wid = threadIdx.x >> 5;
    const int g = lane >> 2, t = lane & 3;
    const int wm0 = (wid >> 1) * 32, wn0 = (wid & 1) * 64;

    #pragma unroll
    for (int mi = 0; mi < 2; mi++)
        #pragma unroll
        for (int ni = 0; ni < 8; ni++) {
            const int n = n0 + wn0 + ni * 8 + t * 2;
            const int h = n >> 6, d0 = n & 63;
            #pragma unroll
            for (int half = 0; half < 2; half++) {
                const int m = m0 + wm0 + mi * 16 + g + half * 8;
                const int b = m >> 11, s = m & (SS - 1);
                float2 v = make_float2(d[mi][ni][half*2] * scale,
                                       d[mi][ni][half*2+1] * scale);
                *(float2*)&outp[(((size_t)(b * HH + h) * SS) + s) * DKK + d0] = v;
            }
        }
}

// ===========================================================================
// Output projection + bias. grid (32, 6), block 256.
// ===========================================================================
__global__ __launch_bounds__(256, 2) void tc_outproj_kernel(
    const float* __restrict__ wo, const float* __restrict__ bo, float* __restrict__ out)
{
    extern __shared__ char smem[];
    const int m0 = blockIdx.x * 128;
    const int n0 = blockIdx.y * 128;

    float d[2][8][4];
    gemm_core(g_att, wo, m0, n0, smem, d);

    const int lane = threadIdx.x & 31, wid = threadIdx.x >> 5;
    const int g = lane >> 2, t = lane & 3;
    const int wm0 = (wid >> 1) * 32, wn0 = (wid & 1) * 64;

    #pragma unroll
    for (int mi = 0; mi < 2; mi++)
        #pragma unroll
        for (int ni = 0; ni < 8; ni++) {
            const int n = n0 + wn0 + ni * 8 + t * 2;
            const float b0v = bo[n], b1v = bo[n + 1];
            #pragma unroll
            for (int half = 0; half < 2; half++) {
                const int m = m0 + wm0 + mi * 16 + g + half * 8;
                *(float2*)&out[(size_t)m * DD + n] =
                    make_float2(d[mi][ni][half*2] + b0v, d[mi][ni][half*2+1] + b1v);
            }
        }
}

// ===========================================================================
// Flash attention (causal), fp32 SIMT — unchanged (port to mma.sync next)
// ===========================================================================
#define ATTN_SMEM_FLOATS (4*64*68 + 3*64)

__global__ __launch_bounds__(256) void attn_kernel()
{
    extern __shared__ float sm[];
    float* Qt   = sm;
    float* Kt   = sm + 64*68;
    float* Vs   = sm + 2*64*68;
    float* Ps   = sm + 3*64*68;
    float* rowm = sm + 4*64*68;
    float* rowl = rowm + 64;
    float* rowa = rowl + 64;

    const int qt = blockIdx.x;
    const int bh = blockIdx.y;
    const float* __restrict__ Qg = g_q + ((size_t)bh * SS + qt * 64) * DKK;
    const float* __restrict__ Kg = g_k + (size_t)bh * SS * DKK;
    const float* __restrict__ Vg = g_v + (size_t)bh * SS * DKK;

    const int tid = threadIdx.x;
    const int ty = tid >> 4, tx = tid & 15;

    for (int u = tid; u < 64 * 16; u += 256) {
        int r = u >> 4, c4 = u & 15;
        float4 v = *(const float4*)&Qg[r * 64 + c4 * 4];
        Qt[(c4*4+0)*68 + r] = v.x; Qt[(c4*4+1)*68 + r] = v.y;
        Qt[(c4*4+2)*68 + r] = v.z; Qt[(c4*4+3)*68 + r] = v.w;
    }
    if (tid < 64) { rowm[tid] = -1e30f; rowl[tid] = 0.0f; }

    float o[4][4] = {};
    __syncthreads();

    for (int kt = 0; kt <= qt; kt++) {
        const float* __restrict__ Kgt = Kg + (size_t)kt * 64 * 64;
        const float* __restrict__ Vgt = Vg + (size_t)kt * 64 * 64;
        for (int u = tid; u < 64 * 16; u += 256) {
            int r = u >> 4, c4 = u & 15;
            float4 kv = *(const float4*)&Kgt[r * 64 + c4 * 4];
            Kt[(c4*4+0)*68 + r] = kv.x; Kt[(c4*4+1)*68 + r] = kv.y;
            Kt[(c4*4+2)*68 + r] = kv.z; Kt[(c4*4+3)*68 + r] = kv.w;
            *(float4*)&Vs[r*68 + c4*4] = *(const float4*)&Vgt[r * 64 + c4 * 4];
        }
        __syncthreads();

        float acc[4][4] = {};
        #pragma unroll 16
        for (int d = 0; d < 64; d++) {
            float4 q = *(const float4*)&Qt[d*68 + ty*4];
            float4 k = *(const float4*)&Kt[d*68 + tx*4];
            acc[0][0] += q.x*k.x; acc[0][1] += q.x*k.y; acc[0][2] += q.x*k.z; acc[0][3] += q.x*k.w;
            acc[1][0] += q.y*k.x; acc[1][1] += q.y*k.y; acc[1][2] += q.y*k.z; acc[1][3] += q.y*k.w;
            acc[2][0] += q.z*k.x; acc[2][1] += q.z*k.y; acc[2][2] += q.z*k.z; acc[2][3] += q.z*k.w;
            acc[3][0] += q.w*k.x; acc[3][1] += q.w*k.y; acc[3][2] += q.w*k.z; acc[3][3] += q.w*k.w;
        }

        if (kt == qt) {
            #pragma unroll
            for (int r = 0; r < 4; r++)
                #pragma unroll
                for (int c = 0; c < 4; c++)
                    if (tx*4 + c > ty*4 + r) acc[r][c] = -1e30f;
        }

        #pragma unroll
        for (int r = 0; r < 4; r++)
            *(float4*)&Ps[(ty*4+r)*68 + tx*4] =
                make_float4(acc[r][0], acc[r][1], acc[r][2], acc[r][3]);
        __syncthreads();

        {
            const int row = tid >> 2, part = tid & 3;
            float* pr = &Ps[row*68 + part*16];
            float mx = -1e30f;
            #pragma unroll
            for (int j = 0; j < 16; j++) mx = fmaxf(mx, pr[j]);
            mx = fmaxf(mx, __shfl_xor_sync(0xffffffffu, mx, 1));
            mx = fmaxf(mx, __shfl_xor_sync(0xffffffffu, mx, 2));
            const float mold = rowm[row];
            const float mnew = fmaxf(mold, mx);
            float sum = 0.0f;
            #pragma unroll
            for (int j = 0; j < 16; j++) {
                float p = __expf(pr[j] - mnew);
                pr[j] = p;
                sum += p;
            }
            sum += __shfl_xor_sync(0xffffffffu, sum, 1);
            sum += __shfl_xor_sync(0xffffffffu, sum, 2);
            if (part == 0) {
                float alpha = __expf(mold - mnew);
                rowa[row] = alpha;
                rowl[row] = rowl[row] * alpha + sum;
                rowm[row] = mnew;
            }
        }
        __syncthreads();

        {
            float a0 = rowa[ty*4+0], a1 = rowa[ty*4+1], a2 = rowa[ty*4+2], a3 = rowa[ty*4+3];
            #pragma unroll
            for (int c = 0; c < 4; c++) { o[0][c]*=a0; o[1][c]*=a1; o[2][c]*=a2; o[3][c]*=a3; }
            #pragma unroll
            for (int j4 = 0; j4 < 16; j4++) {
                float4 v0 = *(const float4*)&Vs[(j4*4+0)*68 + tx*4];
                float4 v1 = *(const float4*)&Vs[(j4*4+1)*68 + tx*4];
                float4 v2 = *(const float4*)&Vs[(j4*4+2)*68 + tx*4];
                float4 v3 = *(const float4*)&Vs[(j4*4+3)*68 + tx*4];
                #pragma unroll
                for (int r = 0; r < 4; r++) {
                    float4 p = *(const float4*)&Ps[(ty*4+r)*68 + j4*4];
                    o[r][0] += p.x*v0.x; o[r][1] += p.x*v0.y; o[r][2] += p.x*v0.z; o[r][3] += p.x*v0.w;
                    o[r][0] += p.y*v1.x; o[r][1] += p.y*v1.y; o[r][2] += p.y*v1.z; o[r][3] += p.y*v1.w;
                    o[r][0] += p.z*v2.x; o[r][1] += p.z*v2.y; o[r][2] += p.z*v2.z; o[r][3] += p.z*v2.w;
                    o[r][0] += p.w*v3.x; o[r][1] += p.w*v3.y; o[r][2] += p.w*v3.z; o[r][3] += p.w*v3.w;
                }
            }
        }
        __syncthreads();
    }

    const int b = bh / HH, h = bh - b * HH;
    #pragma unroll
    for (int r = 0; r < 4; r++) {
        const int sg = qt * 64 + ty * 4 + r;
        const float inv = 1.0f / rowl[ty*4+r];
        *(float4*)&g_att[((size_t)(b * SS + sg)) * DD + h * 64 + tx * 4] =
            make_float4(o[r][0]*inv, o[r][1]*inv, o[r][2]*inv, o[r][3]*inv);
    }
}

// ===========================================================================
extern "C" void kernel_launch(void* const* d_in, const int* in_sizes, int n_in,
                              void* d_out, int out_size)
{
    const float* query = (const float*)d_in[0];
    const float* key   = (const float*)d_in[1];
    const float* value = (const float*)d_in[2];
    // d_in[3] = mask (fixed causal triu, handled analytically)
    const float* wq = (const float*)d_in[4];
    const float* wk = (const float*)d_in[5];
    const float* wv = (const float*)d_in[6];
    const float* wo = (const float*)d_in[7];
    const float* bo = (const float*)d_in[8];
    float* out = (float*)d_out;

    const int attn_smem = ATTN_SMEM_FLOATS * (int)sizeof(float);
    cudaFuncSetAttribute(attn_kernel, cudaFuncAttributeMaxDynamicSharedMemorySize, attn_smem);
    cudaFuncSetAttribute(tc_proj_kernel, cudaFuncAttributeMaxDynamicSharedMemorySize, GEMM_SMEM);
    cudaFuncSetAttribute(tc_outproj_kernel, cudaFuncAttributeMaxDynamicSharedMemorySize, GEMM_SMEM);

    tc_proj_kernel<<<dim3(MM/128, DD/128, 3), 256, GEMM_SMEM>>>(query, key, value, wq, wk, wv);
    attn_kernel<<<dim3(SS/64, BB*HH), 256, attn_smem>>>();
    tc_outproj_kernel<<<dim3(MM/128, DD/128), 256, GEMM_SMEM>>>(wo, bo, out);
}

// round 4
// speedup vs baseline: 2.1457x; 1.6136x over previous
#include <cuda_runtime.h>
#include <cuda_bf16.h>

#define BB 2
#define SS 2048
#define DD 768
#define HH 12
#define DKK 64
#define MM (BB*SS)
#define NCHUNK 12            /* 768 / 64 */

// Scratch: head-split Q/K/V in split-bf16 (hi/lo), attended in fp32
__device__ __nv_bfloat16 g_qh[BB*HH*SS*DKK], g_ql[BB*HH*SS*DKK];
__device__ __nv_bfloat16 g_kh[BB*HH*SS*DKK], g_kl[BB*HH*SS*DKK];
__device__ __nv_bfloat16 g_vh[BB*HH*SS*DKK], g_vl[BB*HH*SS*DKK];
__device__ float g_att[MM*DD];

// ===========================================================================
// Warp-MMA helpers (sm_80-baseline PTX only — no arch-'a' features)
// ===========================================================================
__device__ __forceinline__ unsigned smem_u32(const void* p) {
    unsigned a;
    asm("{ .reg .u64 t; cvta.to.shared.u64 t, %1; cvt.u32.u64 %0, t; }"
        : "=r"(a) : "l"(p));
    return a;
}
__device__ __forceinline__ void ldm_x4(unsigned r[4], unsigned addr) {
    asm volatile("ldmatrix.sync.aligned.m8n8.x4.shared.b16 {%0,%1,%2,%3}, [%4];"
                 : "=r"(r[0]), "=r"(r[1]), "=r"(r[2]), "=r"(r[3]) : "r"(addr));
}
__device__ __forceinline__ void ldm_x4_t(unsigned r[4], unsigned addr) {
    asm volatile("ldmatrix.sync.aligned.m8n8.x4.trans.shared.b16 {%0,%1,%2,%3}, [%4];"
                 : "=r"(r[0]), "=r"(r[1]), "=r"(r[2]), "=r"(r[3]) : "r"(addr));
}
__device__ __forceinline__ void mma_bf16(float d[4], const unsigned a[4],
                                         unsigned b0, unsigned b1) {
    asm volatile(
        "mma.sync.aligned.m16n8k16.row.col.f32.bf16.bf16.f32 "
        "{%0,%1,%2,%3}, {%4,%5,%6,%7}, {%8,%9}, {%0,%1,%2,%3};"
        : "+f"(d[0]), "+f"(d[1]), "+f"(d[2]), "+f"(d[3])
        : "r"(a[0]), "r"(a[1]), "r"(a[2]), "r"(a[3]), "r"(b0), "r"(b1));
}
__device__ __forceinline__ unsigned pk(__nv_bfloat16 a, __nv_bfloat16 b) {
    return (unsigned)__bfloat16_as_ushort(a) | ((unsigned)__bfloat16_as_ushort(b) << 16);
}
__device__ __forceinline__ void split2(float a, float b, unsigned& h, unsigned& l) {
    __nv_bfloat16 ha = __float2bfloat16_rn(a);
    __nv_bfloat16 hb = __float2bfloat16_rn(b);
    h = pk(ha, hb);
    l = pk(__float2bfloat16_rn(a - __bfloat162float(ha)),
           __float2bfloat16_rn(b - __bfloat162float(hb)));
}

// split one fp32 octet into hi/lo bf16 octets (packed)
__device__ __forceinline__ void cvt8(float4 v0, float4 v1, uint4& H, uint4& L) {
    float f[8] = {v0.x, v0.y, v0.z, v0.w, v1.x, v1.y, v1.z, v1.w};
    unsigned h[4], l[4];
    #pragma unroll
    for (int i = 0; i < 4; i++) split2(f[2*i], f[2*i+1], h[i], l[i]);
    H = make_uint4(h[0], h[1], h[2], h[3]);
    L = make_uint4(l[0], l[1], l[2], l[3]);
}

// Load a [128 x 64] fp32 tile, split to hi/lo bf16, store swizzled to smem.
__device__ __forceinline__ void load_tile(const float* __restrict__ src,
                                          int row0, int k0, char* hb, char* lb) {
    const int tid = threadIdx.x;
    #pragma unroll
    for (int i = 0; i < 4; i++) {
        int u = i * 256 + tid;
        int r = u >> 3;
        int o = u & 7;
        const float* p = src + (size_t)(row0 + r) * DD + k0 + o * 8;
        float4 v0 = *(const float4*)p;
        float4 v1 = *(const float4*)(p + 4);
        uint4 H, L;
        cvt8(v0, v1, H, L);
        int off = r * 128 + ((o ^ (r & 7)) * 16);
        *(uint4*)(hb + off) = H;
        *(uint4*)(lb + off) = L;
    }
}

// ===========================================================================
// Split-bf16 GEMM core: D[128x128] = X[128rows x 768] * W[128rows x 768]^T
// ===========================================================================
#define GEMM_SMEM 65536

__device__ __forceinline__ void gemm_core(const float* __restrict__ X,
                                          const float* __restrict__ W,
                                          int m0, int n0, char* smem,
                                          float d[2][8][4]) {
    const int tid = threadIdx.x, lane = tid & 31, wid = tid >> 5;
    const int wm0 = (wid >> 1) * 32;
    const int wn0 = (wid & 1) * 64;
    char* sXh = smem;
    char* sXl = smem + 16384;
    char* sWh = smem + 32768;
    char* sWl = smem + 49152;
    const unsigned uXh = smem_u32(sXh), uXl = smem_u32(sXl);
    const unsigned uWh = smem_u32(sWh), uWl = smem_u32(sWl);

    const int l15 = lane & 15, lhi = lane >> 4, l7 = lane & 7;

    #pragma unroll
    for (int mi = 0; mi < 2; mi++)
        #pragma unroll
        for (int ni = 0; ni < 8; ni++)
            #pragma unroll
            for (int k = 0; k < 4; k++) d[mi][ni][k] = 0.0f;

    for (int c = 0; c < NCHUNK; c++) {
        if (c) __syncthreads();
        load_tile(X, m0, c * 64, sXh, sXl);
        load_tile(W, n0, c * 64, sWh, sWl);
        __syncthreads();

        #pragma unroll
        for (int p = 0; p < 3; p++) {
            const unsigned Ab = (p == 2) ? uXl : uXh;
            const unsigned Bb = (p == 1) ? uWl : uWh;
            #pragma unroll
            for (int ks = 0; ks < 4; ks++) {
                const int sw = (((2 * ks + lhi) ^ l7) * 16);
                unsigned a[2][4], bb[4][4];
                ldm_x4(a[0], Ab + (wm0      + l15) * 128 + sw);
                ldm_x4(a[1], Ab + (wm0 + 16 + l15) * 128 + sw);
                #pragma unroll
                for (int np = 0; np < 4; np++)
                    ldm_x4(bb[np], Bb + (wn0 + np * 16 + l15) * 128 + sw);
                #pragma unroll
                for (int mi = 0; mi < 2; mi++)
                    #pragma unroll
                    for (int np = 0; np < 4; np++) {
                        mma_bf16(d[mi][2*np],     a[mi], bb[np][0], bb[np][2]);
                        mma_bf16(d[mi][2*np + 1], a[mi], bb[np][1], bb[np][3]);
                    }
            }
        }
    }
}

// ===========================================================================
// QKV projection. grid (32, 6, 3), block 256. Writes split-bf16 head-split.
// ===========================================================================
__global__ __launch_bounds__(256, 2) void tc_proj_kernel(
    const float* __restrict__ xq, const float* __restrict__ xk, const float* __restrict__ xv,
    const float* __restrict__ wq, const float* __restrict__ wk, const float* __restrict__ wv)
{
    extern __shared__ char smem[];
    const int z = blockIdx.z;
    const float* __restrict__ x = (z == 0) ? xq : (z == 1) ? xk : xv;
    const float* __restrict__ w = (z == 0) ? wq : (z == 1) ? wk : wv;
    __nv_bfloat16* __restrict__ outH = (z == 0) ? g_qh : (z == 1) ? g_kh : g_vh;
    __nv_bfloat16* __restrict__ outL = (z == 0) ? g_ql : (z == 1) ? g_kl : g_vl;
    const float scale = (z == 0) ? 0.125f : 1.0f;

    const int m0 = blockIdx.x * 128;
    const int n0 = blockIdx.y * 128;

    float d[2][8][4];
    gemm_core(x, w, m0, n0, smem, d);

    const int lane = threadIdx.x & 31, wid = threadIdx.x >> 5;
    const int g = lane >> 2, t = lane & 3;
    const int wm0 = (wid >> 1) * 32, wn0 = (wid & 1) * 64;

    #pragma unroll
    for (int mi = 0; mi < 2; mi++)
        #pragma unroll
        for (int ni = 0; ni < 8; ni++) {
            const int n = n0 + wn0 + ni * 8 + t * 2;
            const int h = n >> 6, d0 = n & 63;
            #pragma unroll
            for (int half = 0; half < 2; half++) {
                const int m = m0 + wm0 + mi * 16 + g + half * 8;
                const int b = m >> 11, s = m & (SS - 1);
                unsigned hi, lo;
                split2(d[mi][ni][half*2] * scale, d[mi][ni][half*2+1] * scale, hi, lo);
                const size_t idx = (((size_t)(b * HH + h) * SS) + s) * DKK + d0;
                *(unsigned*)&outH[idx] = hi;
                *(unsigned*)&outL[idx] = lo;
            }
        }
}

// ===========================================================================
// Output projection + bias. grid (32, 6), block 256.
// ===========================================================================
__global__ __launch_bounds__(256, 2) void tc_outproj_kernel(
    const float* __restrict__ wo, const float* __restrict__ bo, float* __restrict__ out)
{
    extern __shared__ char smem[];
    const int m0 = blockIdx.x * 128;
    const int n0 = blockIdx.y * 128;

    float d[2][8][4];
    gemm_core(g_att, wo, m0, n0, smem, d);

    const int lane = threadIdx.x & 31, wid = threadIdx.x >> 5;
    const int g = lane >> 2, t = lane & 3;
    const int wm0 = (wid >> 1) * 32, wn0 = (wid & 1) * 64;

    #pragma unroll
    for (int mi = 0; mi < 2; mi++)
        #pragma unroll
        for (int ni = 0; ni < 8; ni++) {
            const int n = n0 + wn0 + ni * 8 + t * 2;
            const float b0v = bo[n], b1v = bo[n + 1];
            #pragma unroll
            for (int half = 0; half < 2; half++) {
                const int m = m0 + wm0 + mi * 16 + g + half * 8;
                *(float2*)&out[(size_t)m * DD + n] =
                    make_float2(d[mi][ni][half*2] + b0v, d[mi][ni][half*2+1] + b1v);
            }
        }
}

// ===========================================================================
// Flash attention via mma.sync (split-bf16, causal).
// grid (16, 24), block 256. 128 q-rows per CTA, k-tiles of 64.
// 8 warps x 16 q-rows; per warp: S[16x64] accum, O[16x64] accum.
// ===========================================================================
#define ATTN_SMEM 65536   /* Qh 16K | Ql 16K | Kh 8K | Kl 8K | Vh 8K | Vl 8K */

__global__ __launch_bounds__(256, 2) void attn_mma_kernel()
{
    extern __shared__ char smem[];
    char* sQh = smem;
    char* sQl = smem + 16384;
    char* sKh = smem + 32768;
    char* sKl = smem + 40960;
    char* sVh = smem + 49152;
    char* sVl = smem + 57344;
    const unsigned uQh = smem_u32(sQh), uQl = smem_u32(sQl);
    const unsigned uKh = smem_u32(sKh), uKl = smem_u32(sKl);
    const unsigned uVh = smem_u32(sVh), uVl = smem_u32(sVl);

    const int qt = (int)gridDim.x - 1 - blockIdx.x;   // big tiles first
    const int bh = blockIdx.y;
    const int tid = threadIdx.x, lane = tid & 31, wid = tid >> 5;
    const int l15 = lane & 15, lhi = lane >> 4, l7 = lane & 7;
    const int wm0 = wid * 16;

    const __nv_bfloat16* __restrict__ Qhg = g_qh + ((size_t)bh * SS + qt * 128) * DKK;
    const __nv_bfloat16* __restrict__ Qlg = g_ql + ((size_t)bh * SS + qt * 128) * DKK;
    const __nv_bfloat16* __restrict__ Khg = g_kh + (size_t)bh * SS * DKK;
    const __nv_bfloat16* __restrict__ Klg = g_kl + (size_t)bh * SS * DKK;
    const __nv_bfloat16* __restrict__ Vhg = g_vh + (size_t)bh * SS * DKK;
    const __nv_bfloat16* __restrict__ Vlg = g_vl + (size_t)bh * SS * DKK;

    // ---- load Q tile (hi/lo), swizzled (rows of 128B, 16B chunks) ----
    #pragma unroll
    for (int i = 0; i < 4; i++) {
        int u = i * 256 + tid;          // 0..1023
        int r = u >> 3, o = u & 7;
        int off = r * 128 + ((o ^ (r & 7)) * 16);
        *(uint4*)(sQh + off) = *(const uint4*)(Qhg + r * 64 + o * 8);
        *(uint4*)(sQl + off) = *(const uint4*)(Qlg + r * 64 + o * 8);
    }
    __syncthreads();

    // ---- Q fragments (held for the whole kernel) ----
    unsigned qh[4][4], ql[4][4];
    #pragma unroll
    for (int ks = 0; ks < 4; ks++) {
        const int sw = (((2 * ks + lhi) ^ l7) * 16);
        ldm_x4(qh[ks], uQh + (wm0 + l15) * 128 + sw);
        ldm_x4(ql[ks], uQl + (wm0 + l15) * 128 + sw);
    }

    float o_[8][4];
    #pragma unroll
    for (int t2 = 0; t2 < 8; t2++)
        #pragma unroll
        for (int k = 0; k < 4; k++) o_[t2][k] = 0.0f;
    float m0 = -1e30f, m1 = -1e30f, l0 = 0.0f, l1 = 0.0f;

    const int niter = 2 * qt + 2;
    for (int kt = 0; kt < niter; kt++) {
        __syncthreads();
        // ---- cooperative load K/V tiles (hi/lo), 64x64 each, swizzled ----
        #pragma unroll
        for (int i = 0; i < 2; i++) {
            int u = i * 256 + tid;      // 0..511
            int r = u >> 3, o = u & 7;
            int off = r * 128 + ((o ^ (r & 7)) * 16);
            size_t src = (size_t)(kt * 64 + r) * 64 + o * 8;
            *(uint4*)(sKh + off) = *(const uint4*)(Khg + src);
            *(uint4*)(sKl + off) = *(const uint4*)(Klg + src);
            *(uint4*)(sVh + off) = *(const uint4*)(Vhg + src);
            *(uint4*)(sVl + off) = *(const uint4*)(Vlg + src);
        }
        __syncthreads();

        // upper-diagonal 64-col tile: warps 0-3 (rows < +64) are fully masked
        const bool active = !(kt == 2 * qt + 1 && wid < 4);
        if (!active) continue;

        // ---- S = Q K^T (3 split products) ----
        float s[8][4];
        #pragma unroll
        for (int t2 = 0; t2 < 8; t2++)
            #pragma unroll
            for (int k = 0; k < 4; k++) s[t2][k] = 0.0f;

        #pragma unroll
        for (int ks = 0; ks < 4; ks++) {
            const int sw = (((2 * ks + lhi) ^ l7) * 16);
            #pragma unroll
            for (int np = 0; np < 4; np++) {
                unsigned bh_[4], bl_[4];
                ldm_x4(bh_, uKh + (np * 16 + l15) * 128 + sw);
                ldm_x4(bl_, uKl + (np * 16 + l15) * 128 + sw);
                mma_bf16(s[2*np],   qh[ks], bh_[0], bh_[2]);
                mma_bf16(s[2*np+1], qh[ks], bh_[1], bh_[3]);
                mma_bf16(s[2*np],   qh[ks], bl_[0], bl_[2]);
                mma_bf16(s[2*np+1], qh[ks], bl_[1], bl_[3]);
                mma_bf16(s[2*np],   ql[ks], bh_[0], bh_[2]);
                mma_bf16(s[2*np+1], ql[ks], bh_[1], bh_[3]);
            }
        }

        // ---- causal mask (only near the diagonal) ----
        if (kt >= 2 * qt) {
            const int row0 = qt * 128 + wm0 + (lane >> 2);
            const int colb = kt * 64 + 2 * (lane & 3);
            #pragma unroll
            for (int t2 = 0; t2 < 8; t2++) {
                const int c0 = colb + t2 * 8;
                if (c0     > row0)     s[t2][0] = -1e30f;
                if (c0 + 1 > row0)     s[t2][1] = -1e30f;
                if (c0     > row0 + 8) s[t2][2] = -1e30f;
                if (c0 + 1 > row0 + 8) s[t2][3] = -1e30f;
            }
        }

        // ---- online softmax (rows lane>>2 and +8) ----
        float mx0 = -1e30f, mx1 = -1e30f;
        #pragma unroll
        for (int t2 = 0; t2 < 8; t2++) {
            mx0 = fmaxf(mx0, fmaxf(s[t2][0], s[t2][1]));
            mx1 = fmaxf(mx1, fmaxf(s[t2][2], s[t2][3]));
        }
        mx0 = fmaxf(mx0, __shfl_xor_sync(0xffffffffu, mx0, 1));
        mx0 = fmaxf(mx0, __shfl_xor_sync(0xffffffffu, mx0, 2));
        mx1 = fmaxf(mx1, __shfl_xor_sync(0xffffffffu, mx1, 1));
        mx1 = fmaxf(mx1, __shfl_xor_sync(0xffffffffu, mx1, 2));
        const float mn0 = fmaxf(m0, mx0), mn1 = fmaxf(m1, mx1);
        const float a0 = __expf(m0 - mn0), a1 = __expf(m1 - mn1);
        m0 = mn0; m1 = mn1;

        float sum0 = 0.0f, sum1 = 0.0f;
        #pragma unroll
        for (int t2 = 0; t2 < 8; t2++) {
            s[t2][0] = __expf(s[t2][0] - mn0);
            s[t2][1] = __expf(s[t2][1] - mn0);
            s[t2][2] = __expf(s[t2][2] - mn1);
            s[t2][3] = __expf(s[t2][3] - mn1);
            sum0 += s[t2][0] + s[t2][1];
            sum1 += s[t2][2] + s[t2][3];
        }
        sum0 += __shfl_xor_sync(0xffffffffu, sum0, 1);
        sum0 += __shfl_xor_sync(0xffffffffu, sum0, 2);
        sum1 += __shfl_xor_sync(0xffffffffu, sum1, 1);
        sum1 += __shfl_xor_sync(0xffffffffu, sum1, 2);
        l0 = l0 * a0 + sum0;
        l1 = l1 * a1 + sum1;

        #pragma unroll
        for (int t2 = 0; t2 < 8; t2++) {
            o_[t2][0] *= a0; o_[t2][1] *= a0;
            o_[t2][2] *= a1; o_[t2][3] *= a1;
        }

        // ---- O += P V (3 split products); V B-frags via ldmatrix.trans ----
        #pragma unroll
        for (int ks = 0; ks < 4; ks++) {
            unsigned ph[4], pl[4];
            split2(s[2*ks][0],   s[2*ks][1],   ph[0], pl[0]);
            split2(s[2*ks][2],   s[2*ks][3],   ph[1], pl[1]);
            split2(s[2*ks+1][0], s[2*ks+1][1], ph[2], pl[2]);
            split2(s[2*ks+1][2], s[2*ks+1][3], ph[3], pl[3]);
            #pragma unroll
            for (int dp = 0; dp < 4; dp++) {
                unsigned vh[4], vl[4];
                const int sw = (((2 * dp + lhi) ^ l7) * 16);
                ldm_x4_t(vh, uVh + (ks * 16 + l15) * 128 + sw);
                ldm_x4_t(vl, uVl + (ks * 16 + l15) * 128 + sw);
                mma_bf16(o_[2*dp],   ph, vh[0], vh[1]);
                mma_bf16(o_[2*dp+1], ph, vh[2], vh[3]);
                mma_bf16(o_[2*dp],   ph, vl[0], vl[1]);
                mma_bf16(o_[2*dp+1], ph, vl[2], vl[3]);
                mma_bf16(o_[2*dp],   pl, vh[0], vh[1]);
                mma_bf16(o_[2*dp+1], pl, vh[2], vh[3]);
            }
        }
    }

    // ---- epilogue: normalize, write attended [B*S, D] fp32 ----
    const float inv0 = 1.0f / l0, inv1 = 1.0f / l1;
    const int b = bh / HH, h = bh - b * HH;
    const int row0 = qt * 128 + wm0 + (lane >> 2);
    #pragma unroll
    for (int t2 = 0; t2 < 8; t2++) {
        const int col = h * 64 + t2 * 8 + 2 * (lane & 3);
        *(float2*)&g_att[((size_t)(b * SS + row0)) * DD + col] =
            make_float2(o_[t2][0] * inv0, o_[t2][1] * inv0);
        *(float2*)&g_att[((size_t)(b * SS + row0 + 8)) * DD + col] =
            make_float2(o_[t2][2] * inv1, o_[t2][3] * inv1);
    }
}

// ===========================================================================
extern "C" void kernel_launch(void* const* d_in, const int* in_sizes, int n_in,
                              void* d_out, int out_size)
{
    const float* query = (const float*)d_in[0];
    const float* key   = (const float*)d_in[1];
    const float* value = (const float*)d_in[2];
    // d_in[3] = mask (fixed causal triu, handled analytically)
    const float* wq = (const float*)d_in[4];
    const float* wk = (const float*)d_in[5];
    const float* wv = (const float*)d_in[6];
    const float* wo = (const float*)d_in[7];
    const float* bo = (const float*)d_in[8];
    float* out = (float*)d_out;

    cudaFuncSetAttribute(tc_proj_kernel, cudaFuncAttributeMaxDynamicSharedMemorySize, GEMM_SMEM);
    cudaFuncSetAttribute(tc_outproj_kernel, cudaFuncAttributeMaxDynamicSharedMemorySize, GEMM_SMEM);
    cudaFuncSetAttribute(attn_mma_kernel, cudaFuncAttributeMaxDynamicSharedMemorySize, ATTN_SMEM);

    tc_proj_kernel<<<dim3(MM/128, DD/128, 3), 256, GEMM_SMEM>>>(query, key, value, wq, wk, wv);
    attn_mma_kernel<<<dim3(SS/128, BB*HH), 256, ATTN_SMEM>>>();
    tc_outproj_kernel<<<dim3(MM/128, DD/128), 256, GEMM_SMEM>>>(wo, bo, out);
}

// round 5
// speedup vs baseline: 2.7579x; 1.2853x over previous
#include <cuda_runtime.h>
#include <cuda_bf16.h>

#define BB 2
#define SS 2048
#define DD 768
#define HH 12
#define DKK 64
#define MM (BB*SS)
#define NC32 24             /* 768 / 32 */

// Split-bf16 storage for inputs (3) and weights (4), filled by split_pass
#define XSZ ((size_t)MM*DD)
#define WSZ ((size_t)DD*DD)
#define WOFF (3*XSZ)
__device__ __nv_bfloat16 g_hi[3*XSZ + 4*WSZ];
__device__ __nv_bfloat16 g_lo[3*XSZ + 4*WSZ];

// head-split Q/K/V split-bf16, attended split-bf16
__device__ __nv_bfloat16 g_qh[BB*HH*SS*DKK], g_ql[BB*HH*SS*DKK];
__device__ __nv_bfloat16 g_kh[BB*HH*SS*DKK], g_kl[BB*HH*SS*DKK];
__device__ __nv_bfloat16 g_vh[BB*HH*SS*DKK], g_vl[BB*HH*SS*DKK];
__device__ __nv_bfloat16 g_ah[MM*DD], g_al[MM*DD];

// ===========================================================================
// Helpers (sm_80-baseline PTX only)
// ===========================================================================
__device__ __forceinline__ unsigned smem_u32(const void* p) {
    unsigned a;
    asm("{ .reg .u64 t; cvta.to.shared.u64 t, %1; cvt.u32.u64 %0, t; }"
        : "=r"(a) : "l"(p));
    return a;
}
__device__ __forceinline__ void ldm_x4(unsigned r[4], unsigned addr) {
    asm volatile("ldmatrix.sync.aligned.m8n8.x4.shared.b16 {%0,%1,%2,%3}, [%4];"
                 : "=r"(r[0]), "=r"(r[1]), "=r"(r[2]), "=r"(r[3]) : "r"(addr));
}
__device__ __forceinline__ void ldm_x4_t(unsigned r[4], unsigned addr) {
    asm volatile("ldmatrix.sync.aligned.m8n8.x4.trans.shared.b16 {%0,%1,%2,%3}, [%4];"
                 : "=r"(r[0]), "=r"(r[1]), "=r"(r[2]), "=r"(r[3]) : "r"(addr));
}
__device__ __forceinline__ void mma_bf16(float d[4], const unsigned a[4],
                                         unsigned b0, unsigned b1) {
    asm volatile(
        "mma.sync.aligned.m16n8k16.row.col.f32.bf16.bf16.f32 "
        "{%0,%1,%2,%3}, {%4,%5,%6,%7}, {%8,%9}, {%0,%1,%2,%3};"
        : "+f"(d[0]), "+f"(d[1]), "+f"(d[2]), "+f"(d[3])
        : "r"(a[0]), "r"(a[1]), "r"(a[2]), "r"(a[3]), "r"(b0), "r"(b1));
}
__device__ __forceinline__ void cpa16(unsigned s, const void* g) {
    asm volatile("cp.async.cg.shared.global [%0], [%1], 16;" :: "r"(s), "l"(g));
}
#define CP_COMMIT() asm volatile("cp.async.commit_group;" ::: "memory")
#define CP_WAIT1()  asm volatile("cp.async.wait_group 1;" ::: "memory")
#define CP_WAIT0()  asm volatile("cp.async.wait_group 0;" ::: "memory")

__device__ __forceinline__ unsigned pk(__nv_bfloat16 a, __nv_bfloat16 b) {
    return (unsigned)__bfloat16_as_ushort(a) | ((unsigned)__bfloat16_as_ushort(b) << 16);
}
__device__ __forceinline__ void split2(float a, float b, unsigned& h, unsigned& l) {
    __nv_bfloat16 ha = __float2bfloat16_rn(a);
    __nv_bfloat16 hb = __float2bfloat16_rn(b);
    h = pk(ha, hb);
    l = pk(__float2bfloat16_rn(a - __bfloat162float(ha)),
           __float2bfloat16_rn(b - __bfloat162float(hb)));
}
__device__ __forceinline__ void cvt8(float4 v0, float4 v1, uint4& H, uint4& L) {
    float f[8] = {v0.x, v0.y, v0.z, v0.w, v1.x, v1.y, v1.z, v1.w};
    unsigned h[4], l[4];
    #pragma unroll
    for (int i = 0; i < 4; i++) split2(f[2*i], f[2*i+1], h[i], l[i]);
    H = make_uint4(h[0], h[1], h[2], h[3]);
    L = make_uint4(l[0], l[1], l[2], l[3]);
}

// ===========================================================================
// Pre-split pass: fp32 -> (hi, lo) bf16 for 3 inputs + 4 weights
// ===========================================================================
__global__ __launch_bounds__(256) void split_pass(
    const float* __restrict__ xq, const float* __restrict__ xk, const float* __restrict__ xv,
    const float* __restrict__ wq, const float* __restrict__ wk, const float* __restrict__ wv,
    const float* __restrict__ wo)
{
    const int z = blockIdx.y;
    const float* src;
    size_t off, n;
    if (z < 3) {
        src = (z == 0) ? xq : (z == 1) ? xk : xv;
        off = (size_t)z * XSZ; n = XSZ;
    } else {
        src = (z == 3) ? wq : (z == 4) ? wk : (z == 5) ? wv : wo;
        off = WOFF + (size_t)(z - 3) * WSZ; n = WSZ;
    }
    size_t i = ((size_t)blockIdx.x * 256 + threadIdx.x) * 8;
    if (i >= n) return;
    float4 v0 = *(const float4*)(src + i);
    float4 v1 = *(const float4*)(src + i + 4);
    uint4 H, L;
    cvt8(v0, v1, H, L);
    *(uint4*)&g_hi[off + i] = H;
    *(uint4*)&g_lo[off + i] = L;
}

// ===========================================================================
// cp.async double-buffered split-bf16 GEMM: D[128x128] = A[128,768] B[128,768]^T
// K-chunk 32, stage = Ah|Al|Bh|Bl 8KB each (64B rows, swizzle o^((r>>1)&3)).
// ===========================================================================
#define GEMM_SMEM 65536

__device__ __forceinline__ void gemm_issue(
    const __nv_bfloat16* __restrict__ Ah, const __nv_bfloat16* __restrict__ Al,
    const __nv_bfloat16* __restrict__ Bh, const __nv_bfloat16* __restrict__ Bl,
    int m0, int n0, int k0, unsigned dst)
{
    const int tid = threadIdx.x;
    #pragma unroll
    for (int j = 0; j < 2; j++) {
        int u = tid + j * 256, r = u >> 2, o = u & 3;
        unsigned off = r * 64 + ((o ^ ((r >> 1) & 3)) * 16);
        int co = k0 + o * 8;
        cpa16(dst +         off, Ah + (size_t)(m0 + r) * DD + co);
        cpa16(dst +  8192 + off, Al + (size_t)(m0 + r) * DD + co);
        cpa16(dst + 16384 + off, Bh + (size_t)(n0 + r) * DD + co);
        cpa16(dst + 24576 + off, Bl + (size_t)(n0 + r) * DD + co);
    }
}

__device__ __forceinline__ void gemm_core(
    const __nv_bfloat16* __restrict__ Ah, const __nv_bfloat16* __restrict__ Al,
    const __nv_bfloat16* __restrict__ Bh, const __nv_bfloat16* __restrict__ Bl,
    int m0, int n0, unsigned uS, float d[2][8][4])
{
    const int tid = threadIdx.x, lane = tid & 31, wid = tid >> 5;
    const int wm0 = (wid >> 1) * 32, wn0 = (wid & 1) * 64;
    const int l15 = lane & 15, lhi = lane >> 4;

    #pragma unroll
    for (int mi = 0; mi < 2; mi++)
        #pragma unroll
        for (int ni = 0; ni < 8; ni++)
            #pragma unroll
            for (int k = 0; k < 4; k++) d[mi][ni][k] = 0.0f;

    gemm_issue(Ah, Al, Bh, Bl, m0, n0, 0,  uS);          CP_COMMIT();
    gemm_issue(Ah, Al, Bh, Bl, m0, n0, 32, uS + 32768);  CP_COMMIT();

    const int rA0 = wm0 + l15, rA1 = wm0 + 16 + l15;

    for (int c = 0; c < NC32; c++) {
        if (c + 1 < NC32) CP_WAIT1(); else CP_WAIT0();
        __syncthreads();
        const unsigned base = uS + (c & 1) * 32768;

        #pragma unroll
        for (int ks = 0; ks < 2; ks++) {
            const int swk = 2 * ks + lhi;
            unsigned a0 = base + rA0 * 64 + ((swk ^ ((rA0 >> 1) & 3)) * 16);
            unsigned a1 = base + rA1 * 64 + ((swk ^ ((rA1 >> 1) & 3)) * 16);
            unsigned ah0[4], ah1[4], al0[4], al1[4];
            ldm_x4(ah0, a0);        ldm_x4(ah1, a1);
            ldm_x4(al0, a0 + 8192); ldm_x4(al1, a1 + 8192);
            unsigned bh[4][4], bl[4][4];
            #pragma unroll
            for (int np = 0; np < 4; np++) {
                int rB = wn0 + np * 16 + l15;
                unsigned bo = base + 16384 + rB * 64 + ((swk ^ ((rB >> 1) & 3)) * 16);
                ldm_x4(bh[np], bo);
                ldm_x4(bl[np], bo + 8192);
            }
            #pragma unroll
            for (int np = 0; np < 4; np++) {
                mma_bf16(d[0][2*np],   ah0, bh[np][0], bh[np][2]);
                mma_bf16(d[0][2*np+1], ah0, bh[np][1], bh[np][3]);
                mma_bf16(d[1][2*np],   ah1, bh[np][0], bh[np][2]);
                mma_bf16(d[1][2*np+1], ah1, bh[np][1], bh[np][3]);
                mma_bf16(d[0][2*np],   ah0, bl[np][0], bl[np][2]);
                mma_bf16(d[0][2*np+1], ah0, bl[np][1], bl[np][3]);
                mma_bf16(d[1][2*np],   ah1, bl[np][0], bl[np][2]);
                mma_bf16(d[1][2*np+1], ah1, bl[np][1], bl[np][3]);
                mma_bf16(d[0][2*np],   al0, bh[np][0], bh[np][2]);
                mma_bf16(d[0][2*np+1], al0, bh[np][1], bh[np][3]);
                mma_bf16(d[1][2*np],   al1, bh[np][0], bh[np][2]);
                mma_bf16(d[1][2*np+1], al1, bh[np][1], bh[np][3]);
            }
        }
        __syncthreads();
        if (c + 2 < NC32) {
            gemm_issue(Ah, Al, Bh, Bl, m0, n0, (c + 2) * 32, base);
            CP_COMMIT();
        }
    }
}

// ===========================================================================
// QKV projection. grid (32, 6, 3), block 256. Writes split-bf16 head-split.
// ===========================================================================
__global__ __launch_bounds__(256, 2) void tc_proj_kernel()
{
    extern __shared__ char smem[];
    const unsigned uS = smem_u32(smem);
    const int z = blockIdx.z;
    const __nv_bfloat16* Xh = g_hi + (size_t)z * XSZ;
    const __nv_bfloat16* Xl = g_lo + (size_t)z * XSZ;
    const __nv_bfloat16* Wh = g_hi + WOFF + (size_t)z * WSZ;
    const __nv_bfloat16* Wl = g_lo + WOFF + (size_t)z * WSZ;
    __nv_bfloat16* __restrict__ outH = (z == 0) ? g_qh : (z == 1) ? g_kh : g_vh;
    __nv_bfloat16* __restrict__ outL = (z == 0) ? g_ql : (z == 1) ? g_kl : g_vl;
    const float scale = (z == 0) ? 0.125f : 1.0f;

    const int m0 = blockIdx.x * 128;
    const int n0 = blockIdx.y * 128;

    float d[2][8][4];
    gemm_core(Xh, Xl, Wh, Wl, m0, n0, uS, d);

    const int lane = threadIdx.x & 31, wid = threadIdx.x >> 5;
    const int g = lane >> 2, t = lane & 3;
    const int wm0 = (wid >> 1) * 32, wn0 = (wid & 1) * 64;

    #pragma unroll
    for (int mi = 0; mi < 2; mi++)
        #pragma unroll
        for (int ni = 0; ni < 8; ni++) {
            const int n = n0 + wn0 + ni * 8 + t * 2;
            const int h = n >> 6, d0 = n & 63;
            #pragma unroll
            for (int half = 0; half < 2; half++) {
                const int m = m0 + wm0 + mi * 16 + g + half * 8;
                const int b = m >> 11, s = m & (SS - 1);
                unsigned hi, lo;
                split2(d[mi][ni][half*2] * scale, d[mi][ni][half*2+1] * scale, hi, lo);
                const size_t idx = (((size_t)(b * HH + h) * SS) + s) * DKK + d0;
                *(unsigned*)&outH[idx] = hi;
                *(unsigned*)&outL[idx] = lo;
            }
        }
}

// ===========================================================================
// Output projection + bias. grid (32, 6), block 256.
// ===========================================================================
__global__ __launch_bounds__(256, 2) void tc_outproj_kernel(
    const float* __restrict__ bo, float* __restrict__ out)
{
    extern __shared__ char smem[];
    const unsigned uS = smem_u32(smem);
    const int m0 = blockIdx.x * 128;
    const int n0 = blockIdx.y * 128;

    float d[2][8][4];
    gemm_core(g_ah, g_al, g_hi + WOFF + 3 * WSZ, g_lo + WOFF + 3 * WSZ,
              m0, n0, uS, d);

    const int lane = threadIdx.x & 31, wid = threadIdx.x >> 5;
    const int g = lane >> 2, t = lane & 3;
    const int wm0 = (wid >> 1) * 32, wn0 = (wid & 1) * 64;

    #pragma unroll
    for (int mi = 0; mi < 2; mi++)
        #pragma unroll
        for (int ni = 0; ni < 8; ni++) {
            const int n = n0 + wn0 + ni * 8 + t * 2;
            const float b0v = bo[n], b1v = bo[n + 1];
            #pragma unroll
            for (int half = 0; half < 2; half++) {
                const int m = m0 + wm0 + mi * 16 + g + half * 8;
                *(float2*)&out[(size_t)m * DD + n] =
                    make_float2(d[mi][ni][half*2] + b0v, d[mi][ni][half*2+1] + b1v);
            }
        }
}

// ===========================================================================
// Flash attention (split-bf16 mma.sync, causal) with cp.async K/V pipeline.
// grid (16, 24), block 256. Q 32KB + 2 stages x 32KB (Kh|Kl|Vh|Vl 8KB each).
// ===========================================================================
#define ATTN_SMEM 98304

__device__ __forceinline__ void attn_issue(
    const __nv_bfloat16* __restrict__ Khg, const __nv_bfloat16* __restrict__ Klg,
    const __nv_bfloat16* __restrict__ Vhg, const __nv_bfloat16* __restrict__ Vlg,
    int kt, unsigned dst)
{
    const int tid = threadIdx.x;
    #pragma unroll
    for (int j = 0; j < 2; j++) {
        int u = tid + j * 256, r = u >> 3, o = u & 7;
        unsigned off = r * 128 + ((o ^ (r & 7)) * 16);
        size_t src = (size_t)(kt * 64 + r) * 64 + o * 8;
        cpa16(dst +         off, Khg + src);
        cpa16(dst +  8192 + off, Klg + src);
        cpa16(dst + 16384 + off, Vhg + src);
        cpa16(dst + 24576 + off, Vlg + src);
    }
}

__global__ __launch_bounds__(256, 2) void attn_mma_kernel()
{
    extern __shared__ char smem[];
    const unsigned uS = smem_u32(smem);
    const unsigned uQh = uS, uQl = uS + 16384;
    const unsigned uKV = uS + 32768;

    const int qt = (int)gridDim.x - 1 - blockIdx.x;   // big tiles first
    const int bh = blockIdx.y;
    const int tid = threadIdx.x, lane = tid & 31, wid = tid >> 5;
    const int l15 = lane & 15, lhi = lane >> 4, l7 = lane & 7;
    const int wm0 = wid * 16;

    const __nv_bfloat16* __restrict__ Qhg = g_qh + ((size_t)bh * SS + qt * 128) * DKK;
    const __nv_bfloat16* __restrict__ Qlg = g_ql + ((size_t)bh * SS + qt * 128) * DKK;
    const __nv_bfloat16* __restrict__ Khg = g_kh + (size_t)bh * SS * DKK;
    const __nv_bfloat16* __restrict__ Klg = g_kl + (size_t)bh * SS * DKK;
    const __nv_bfloat16* __restrict__ Vhg = g_vh + (size_t)bh * SS * DKK;
    const __nv_bfloat16* __restrict__ Vlg = g_vl + (size_t)bh * SS * DKK;

    const int niter = 2 * qt + 2;

    // prologue: start K/V pipeline, then load Q while it flies
    attn_issue(Khg, Klg, Vhg, Vlg, 0, uKV);          CP_COMMIT();
    attn_issue(Khg, Klg, Vhg, Vlg, 1, uKV + 32768);  CP_COMMIT();

    #pragma unroll
    for (int i = 0; i < 4; i++) {
        int u = i * 256 + tid;
        int r = u >> 3, o = u & 7;
        int off = r * 128 + ((o ^ (r & 7)) * 16);
        *(uint4*)(smem + off)         = *(const uint4*)(Qhg + r * 64 + o * 8);
        *(uint4*)(smem + 16384 + off) = *(const uint4*)(Qlg + r * 64 + o * 8);
    }
    __syncthreads();

    unsigned qh[4][4], ql[4][4];
    #pragma unroll
    for (int ks = 0; ks < 4; ks++) {
        const int sw = (((2 * ks + lhi) ^ l7) * 16);
        ldm_x4(qh[ks], uQh + (wm0 + l15) * 128 + sw);
        ldm_x4(ql[ks], uQl + (wm0 + l15) * 128 + sw);
    }

    float o_[8][4];
    #pragma unroll
    for (int t2 = 0; t2 < 8; t2++)
        #pragma unroll
        for (int k = 0; k < 4; k++) o_[t2][k] = 0.0f;
    float m0 = -1e30f, m1 = -1e30f, l0 = 0.0f, l1 = 0.0f;

    for (int kt = 0; kt < niter; kt++) {
        if (kt + 1 < niter) CP_WAIT1(); else CP_WAIT0();
        __syncthreads();
        const unsigned kb = uKV + (kt & 1) * 32768;
        const unsigned uKh = kb, uKl = kb + 8192, uVh = kb + 16384, uVl = kb + 24576;

        const bool active = !(kt == 2 * qt + 1 && wid < 4);
        if (active) {
            // ---- S = Q K^T (3 split products) ----
            float s[8][4];
            #pragma unroll
            for (int t2 = 0; t2 < 8; t2++)
                #pragma unroll
                for (int k = 0; k < 4; k++) s[t2][k] = 0.0f;

            #pragma unroll
            for (int ks = 0; ks < 4; ks++) {
                const int sw = (((2 * ks + lhi) ^ l7) * 16);
                #pragma unroll
                for (int np = 0; np < 4; np++) {
                    unsigned bh_[4], bl_[4];
                    ldm_x4(bh_, uKh + (np * 16 + l15) * 128 + sw);
                    ldm_x4(bl_, uKl + (np * 16 + l15) * 128 + sw);
                    mma_bf16(s[2*np],   qh[ks], bh_[0], bh_[2]);
                    mma_bf16(s[2*np+1], qh[ks], bh_[1], bh_[3]);
                    mma_bf16(s[2*np],   qh[ks], bl_[0], bl_[2]);
                    mma_bf16(s[2*np+1], qh[ks], bl_[1], bl_[3]);
                    mma_bf16(s[2*np],   ql[ks], bh_[0], bh_[2]);
                    mma_bf16(s[2*np+1], ql[ks], bh_[1], bh_[3]);
                }
            }

            // ---- causal mask near diagonal ----
            if (kt >= 2 * qt) {
                const int row0 = qt * 128 + wm0 + (lane >> 2);
                const int colb = kt * 64 + 2 * (lane & 3);
                #pragma unroll
                for (int t2 = 0; t2 < 8; t2++) {
                    const int c0 = colb + t2 * 8;
                    if (c0     > row0)     s[t2][0] = -1e30f;
                    if (c0 + 1 > row0)     s[t2][1] = -1e30f;
                    if (c0     > row0 + 8) s[t2][2] = -1e30f;
                    if (c0 + 1 > row0 + 8) s[t2][3] = -1e30f;
                }
            }

            // ---- online softmax ----
            float mx0 = -1e30f, mx1 = -1e30f;
            #pragma unroll
            for (int t2 = 0; t2 < 8; t2++) {
                mx0 = fmaxf(mx0, fmaxf(s[t2][0], s[t2][1]));
                mx1 = fmaxf(mx1, fmaxf(s[t2][2], s[t2][3]));
            }
            mx0 = fmaxf(mx0, __shfl_xor_sync(0xffffffffu, mx0, 1));
            mx0 = fmaxf(mx0, __shfl_xor_sync(0xffffffffu, mx0, 2));
            mx1 = fmaxf(mx1, __shfl_xor_sync(0xffffffffu, mx1, 1));
            mx1 = fmaxf(mx1, __shfl_xor_sync(0xffffffffu, mx1, 2));
            const float mn0 = fmaxf(m0, mx0), mn1 = fmaxf(m1, mx1);
            const float a0 = __expf(m0 - mn0), a1 = __expf(m1 - mn1);
            m0 = mn0; m1 = mn1;

            float sum0 = 0.0f, sum1 = 0.0f;
            #pragma unroll
            for (int t2 = 0; t2 < 8; t2++) {
                s[t2][0] = __expf(s[t2][0] - mn0);
                s[t2][1] = __expf(s[t2][1] - mn0);
                s[t2][2] = __expf(s[t2][2] - mn1);
                s[t2][3] = __expf(s[t2][3] - mn1);
                sum0 += s[t2][0] + s[t2][1];
                sum1 += s[t2][2] + s[t2][3];
            }
            sum0 += __shfl_xor_sync(0xffffffffu, sum0, 1);
            sum0 += __shfl_xor_sync(0xffffffffu, sum0, 2);
            sum1 += __shfl_xor_sync(0xffffffffu, sum1, 1);
            sum1 += __shfl_xor_sync(0xffffffffu, sum1, 2);
            l0 = l0 * a0 + sum0;
            l1 = l1 * a1 + sum1;

            #pragma unroll
            for (int t2 = 0; t2 < 8; t2++) {
                o_[t2][0] *= a0; o_[t2][1] *= a0;
                o_[t2][2] *= a1; o_[t2][3] *= a1;
            }

            // ---- O += P V (3 split products) ----
            #pragma unroll
            for (int ks = 0; ks < 4; ks++) {
                unsigned ph[4], pl[4];
                split2(s[2*ks][0],   s[2*ks][1],   ph[0], pl[0]);
                split2(s[2*ks][2],   s[2*ks][3],   ph[1], pl[1]);
                split2(s[2*ks+1][0], s[2*ks+1][1], ph[2], pl[2]);
                split2(s[2*ks+1][2], s[2*ks+1][3], ph[3], pl[3]);
                #pragma unroll
                for (int dp = 0; dp < 4; dp++) {
                    unsigned vh[4], vl[4];
                    const int sw = (((2 * dp + lhi) ^ l7) * 16);
                    ldm_x4_t(vh, uVh + (ks * 16 + l15) * 128 + sw);
                    ldm_x4_t(vl, uVl + (ks * 16 + l15) * 128 + sw);
                    mma_bf16(o_[2*dp],   ph, vh[0], vh[1]);
                    mma_bf16(o_[2*dp+1], ph, vh[2], vh[3]);
                    mma_bf16(o_[2*dp],   ph, vl[0], vl[1]);
                    mma_bf16(o_[2*dp+1], ph, vl[2], vl[3]);
                    mma_bf16(o_[2*dp],   pl, vh[0], vh[1]);
                    mma_bf16(o_[2*dp+1], pl, vh[2], vh[3]);
                }
            }
        }
        __syncthreads();
        if (kt + 2 < niter) {
            attn_issue(Khg, Klg, Vhg, Vlg, kt + 2, uKV + (kt & 1) * 32768);
            CP_COMMIT();
        }
    }

    // ---- epilogue: normalize, write attended split-bf16 [B*S, D] ----
    const float inv0 = 1.0f / l0, inv1 = 1.0f / l1;
    const int b = bh / HH, h = bh - b * HH;
    const int row0 = qt * 128 + wm0 + (lane >> 2);
    #pragma unroll
    for (int t2 = 0; t2 < 8; t2++) {
        const int col = h * 64 + t2 * 8 + 2 * (lane & 3);
        unsigned hi, lo;
        split2(o_[t2][0] * inv0, o_[t2][1] * inv0, hi, lo);
        size_t i0 = ((size_t)(b * SS + row0)) * DD + col;
        *(unsigned*)&g_ah[i0] = hi;
        *(unsigned*)&g_al[i0] = lo;
        split2(o_[t2][2] * inv1, o_[t2][3] * inv1, hi, lo);
        size_t i1 = ((size_t)(b * SS + row0 + 8)) * DD + col;
        *(unsigned*)&g_ah[i1] = hi;
        *(unsigned*)&g_al[i1] = lo;
    }
}

// ===========================================================================
extern "C" void kernel_launch(void* const* d_in, const int* in_sizes, int n_in,
                              void* d_out, int out_size)
{
    const float* query = (const float*)d_in[0];
    const float* key   = (const float*)d_in[1];
    const float* value = (const float*)d_in[2];
    // d_in[3] = mask (fixed causal triu, handled analytically)
    const float* wq = (const float*)d_in[4];
    const float* wk = (const float*)d_in[5];
    const float* wv = (const float*)d_in[6];
    const float* wo = (const float*)d_in[7];
    const float* bo = (const float*)d_in[8];
    float* out = (float*)d_out;

    cudaFuncSetAttribute(tc_proj_kernel, cudaFuncAttributeMaxDynamicSharedMemorySize, GEMM_SMEM);
    cudaFuncSetAttribute(tc_outproj_kernel, cudaFuncAttributeMaxDynamicSharedMemorySize, GEMM_SMEM);
    cudaFuncSetAttribute(attn_mma_kernel, cudaFuncAttributeMaxDynamicSharedMemorySize, ATTN_SMEM);

    split_pass<<<dim3((int)(XSZ/8/256), 7), 256>>>(query, key, value, wq, wk, wv, wo);
    tc_proj_kernel<<<dim3(MM/128, DD/128, 3), 256, GEMM_SMEM>>>();
    attn_mma_kernel<<<dim3(SS/128, BB*HH), 256, ATTN_SMEM>>>();
    tc_outproj_kernel<<<dim3(MM/128, DD/128), 256, GEMM_SMEM>>>(bo, out);
}

// round 6
// speedup vs baseline: 2.8457x; 1.0318x over previous
#include <cuda_runtime.h>
#include <cuda_bf16.h>

#define BB 2
#define SS 2048
#define DD 768
#define HH 12
#define DKK 64
#define MM (BB*SS)
#define NC32 24             /* 768 / 32 */

// Split-bf16 storage for inputs (3) and weights (4), filled by split_pass
#define XSZ ((size_t)MM*DD)
#define WSZ ((size_t)DD*DD)
#define WOFF (3*XSZ)
__device__ __nv_bfloat16 g_hi[3*XSZ + 4*WSZ];
__device__ __nv_bfloat16 g_lo[3*XSZ + 4*WSZ];

// head-split Q/K/V split-bf16, attended split-bf16
__device__ __nv_bfloat16 g_qh[BB*HH*SS*DKK], g_ql[BB*HH*SS*DKK];
__device__ __nv_bfloat16 g_kh[BB*HH*SS*DKK], g_kl[BB*HH*SS*DKK];
__device__ __nv_bfloat16 g_vh[BB*HH*SS*DKK], g_vl[BB*HH*SS*DKK];
__device__ __nv_bfloat16 g_ah[MM*DD], g_al[MM*DD];

// ===========================================================================
// Helpers (sm_80-baseline PTX only)
// ===========================================================================
__device__ __forceinline__ unsigned smem_u32(const void* p) {
    unsigned a;
    asm("{ .reg .u64 t; cvta.to.shared.u64 t, %1; cvt.u32.u64 %0, t; }"
        : "=r"(a) : "l"(p));
    return a;
}
__device__ __forceinline__ void ldm_x4(unsigned r[4], unsigned addr) {
    asm volatile("ldmatrix.sync.aligned.m8n8.x4.shared.b16 {%0,%1,%2,%3}, [%4];"
                 : "=r"(r[0]), "=r"(r[1]), "=r"(r[2]), "=r"(r[3]) : "r"(addr));
}
__device__ __forceinline__ void ldm_x4_t(unsigned r[4], unsigned addr) {
    asm volatile("ldmatrix.sync.aligned.m8n8.x4.trans.shared.b16 {%0,%1,%2,%3}, [%4];"
                 : "=r"(r[0]), "=r"(r[1]), "=r"(r[2]), "=r"(r[3]) : "r"(addr));
}
__device__ __forceinline__ void mma_bf16(float d[4], const unsigned a[4],
                                         unsigned b0, unsigned b1) {
    asm volatile(
        "mma.sync.aligned.m16n8k16.row.col.f32.bf16.bf16.f32 "
        "{%0,%1,%2,%3}, {%4,%5,%6,%7}, {%8,%9}, {%0,%1,%2,%3};"
        : "+f"(d[0]), "+f"(d[1]), "+f"(d[2]), "+f"(d[3])
        : "r"(a[0]), "r"(a[1]), "r"(a[2]), "r"(a[3]), "r"(b0), "r"(b1));
}
__device__ __forceinline__ void cpa16(unsigned s, const void* g) {
    asm volatile("cp.async.cg.shared.global [%0], [%1], 16;" :: "r"(s), "l"(g));
}
#define CP_COMMIT() asm volatile("cp.async.commit_group;" ::: "memory")
#define CP_WAIT1()  asm volatile("cp.async.wait_group 1;" ::: "memory")
#define CP_WAIT0()  asm volatile("cp.async.wait_group 0;" ::: "memory")

__device__ __forceinline__ unsigned pk(__nv_bfloat16 a, __nv_bfloat16 b) {
    return (unsigned)__bfloat16_as_ushort(a) | ((unsigned)__bfloat16_as_ushort(b) << 16);
}
__device__ __forceinline__ void split2(float a, float b, unsigned& h, unsigned& l) {
    __nv_bfloat16 ha = __float2bfloat16_rn(a);
    __nv_bfloat16 hb = __float2bfloat16_rn(b);
    h = pk(ha, hb);
    l = pk(__float2bfloat16_rn(a - __bfloat162float(ha)),
           __float2bfloat16_rn(b - __bfloat162float(hb)));
}
__device__ __forceinline__ void cvt8(float4 v0, float4 v1, uint4& H, uint4& L) {
    float f[8] = {v0.x, v0.y, v0.z, v0.w, v1.x, v1.y, v1.z, v1.w};
    unsigned h[4], l[4];
    #pragma unroll
    for (int i = 0; i < 4; i++) split2(f[2*i], f[2*i+1], h[i], l[i]);
    H = make_uint4(h[0], h[1], h[2], h[3]);
    L = make_uint4(l[0], l[1], l[2], l[3]);
}

// ===========================================================================
// Pre-split pass: fp32 -> (hi, lo) bf16 for 3 inputs + 4 weights
// ===========================================================================
__global__ __launch_bounds__(256) void split_pass(
    const float* __restrict__ xq, const float* __restrict__ xk, const float* __restrict__ xv,
    const float* __restrict__ wq, const float* __restrict__ wk, const float* __restrict__ wv,
    const float* __restrict__ wo)
{
    const int z = blockIdx.y;
    const float* src;
    size_t off, n;
    if (z < 3) {
        src = (z == 0) ? xq : (z == 1) ? xk : xv;
        off = (size_t)z * XSZ; n = XSZ;
    } else {
        src = (z == 3) ? wq : (z == 4) ? wk : (z == 5) ? wv : wo;
        off = WOFF + (size_t)(z - 3) * WSZ; n = WSZ;
    }
    size_t i = ((size_t)blockIdx.x * 256 + threadIdx.x) * 8;
    if (i >= n) return;
    float4 v0 = *(const float4*)(src + i);
    float4 v1 = *(const float4*)(src + i + 4);
    uint4 H, L;
    cvt8(v0, v1, H, L);
    *(uint4*)&g_hi[off + i] = H;
    *(uint4*)&g_lo[off + i] = L;
}

// ===========================================================================
// 3-stage cp.async split-bf16 GEMM: D[128x128] = A[128,768] B[128,768]^T
// K-chunk 32, stage = Ah|Al|Bh|Bl 8KB each (64B rows, swizzle o^((r>>1)&3)).
// Single __syncthreads per iteration (issue-before-compute).
// ===========================================================================
#define GEMM_SMEM 98304

__device__ __forceinline__ void gemm_issue(
    const __nv_bfloat16* __restrict__ Ah, const __nv_bfloat16* __restrict__ Al,
    const __nv_bfloat16* __restrict__ Bh, const __nv_bfloat16* __restrict__ Bl,
    int m0, int n0, int k0, unsigned dst)
{
    const int tid = threadIdx.x;
    #pragma unroll
    for (int j = 0; j < 2; j++) {
        int u = tid + j * 256, r = u >> 2, o = u & 3;
        unsigned off = r * 64 + ((o ^ ((r >> 1) & 3)) * 16);
        int co = k0 + o * 8;
        cpa16(dst +         off, Ah + (size_t)(m0 + r) * DD + co);
        cpa16(dst +  8192 + off, Al + (size_t)(m0 + r) * DD + co);
        cpa16(dst + 16384 + off, Bh + (size_t)(n0 + r) * DD + co);
        cpa16(dst + 24576 + off, Bl + (size_t)(n0 + r) * DD + co);
    }
}

__device__ __forceinline__ void gemm_core(
    const __nv_bfloat16* __restrict__ Ah, const __nv_bfloat16* __restrict__ Al,
    const __nv_bfloat16* __restrict__ Bh, const __nv_bfloat16* __restrict__ Bl,
    int m0, int n0, unsigned uS, float d[2][8][4])
{
    const int tid = threadIdx.x, lane = tid & 31, wid = tid >> 5;
    const int wm0 = (wid >> 1) * 32, wn0 = (wid & 1) * 64;
    const int l15 = lane & 15, lhi = lane >> 4;

    #pragma unroll
    for (int mi = 0; mi < 2; mi++)
        #pragma unroll
        for (int ni = 0; ni < 8; ni++)
            #pragma unroll
            for (int k = 0; k < 4; k++) d[mi][ni][k] = 0.0f;

    gemm_issue(Ah, Al, Bh, Bl, m0, n0, 0,  uS);          CP_COMMIT();
    gemm_issue(Ah, Al, Bh, Bl, m0, n0, 32, uS + 32768);  CP_COMMIT();

    const int rA0 = wm0 + l15, rA1 = wm0 + 16 + l15;

    for (int c = 0; c < NC32; c++) {
        if (c + 1 < NC32) CP_WAIT1(); else CP_WAIT0();
        __syncthreads();
        // prefetch chunk c+2 into the stage compute c-1 just vacated
        if (c + 2 < NC32) {
            gemm_issue(Ah, Al, Bh, Bl, m0, n0, (c + 2) * 32,
                       uS + ((c + 2) % 3) * 32768);
            CP_COMMIT();
        }
        const unsigned base = uS + (c % 3) * 32768;

        #pragma unroll
        for (int ks = 0; ks < 2; ks++) {
            const int swk = 2 * ks + lhi;
            unsigned a0 = base + rA0 * 64 + ((swk ^ ((rA0 >> 1) & 3)) * 16);
            unsigned a1 = base + rA1 * 64 + ((swk ^ ((rA1 >> 1) & 3)) * 16);
            unsigned ah0[4], ah1[4], al0[4], al1[4];
            ldm_x4(ah0, a0);        ldm_x4(ah1, a1);
            ldm_x4(al0, a0 + 8192); ldm_x4(al1, a1 + 8192);
            unsigned bh[4][4], bl[4][4];
            #pragma unroll
            for (int np = 0; np < 4; np++) {
                int rB = wn0 + np * 16 + l15;
                unsigned bo = base + 16384 + rB * 64 + ((swk ^ ((rB >> 1) & 3)) * 16);
                ldm_x4(bh[np], bo);
                ldm_x4(bl[np], bo + 8192);
            }
            #pragma unroll
            for (int np = 0; np < 4; np++) {
                mma_bf16(d[0][2*np],   ah0, bh[np][0], bh[np][2]);
                mma_bf16(d[0][2*np+1], ah0, bh[np][1], bh[np][3]);
                mma_bf16(d[1][2*np],   ah1, bh[np][0], bh[np][2]);
                mma_bf16(d[1][2*np+1], ah1, bh[np][1], bh[np][3]);
                mma_bf16(d[0][2*np],   ah0, bl[np][0], bl[np][2]);
                mma_bf16(d[0][2*np+1], ah0, bl[np][1], bl[np][3]);
                mma_bf16(d[1][2*np],   ah1, bl[np][0], bl[np][2]);
                mma_bf16(d[1][2*np+1], ah1, bl[np][1], bl[np][3]);
                mma_bf16(d[0][2*np],   al0, bh[np][0], bh[np][2]);
                mma_bf16(d[0][2*np+1], al0, bh[np][1], bh[np][3]);
                mma_bf16(d[1][2*np],   al1, bh[np][0], bh[np][2]);
                mma_bf16(d[1][2*np+1], al1, bh[np][1], bh[np][3]);
            }
        }
    }
}

// ===========================================================================
// QKV projection. grid (32, 6, 3), block 256. Writes split-bf16 head-split.
// ===========================================================================
__global__ __launch_bounds__(256, 2) void tc_proj_kernel()
{
    extern __shared__ char smem[];
    const unsigned uS = smem_u32(smem);
    const int z = blockIdx.z;
    const __nv_bfloat16* Xh = g_hi + (size_t)z * XSZ;
    const __nv_bfloat16* Xl = g_lo + (size_t)z * XSZ;
    const __nv_bfloat16* Wh = g_hi + WOFF + (size_t)z * WSZ;
    const __nv_bfloat16* Wl = g_lo + WOFF + (size_t)z * WSZ;
    __nv_bfloat16* __restrict__ outH = (z == 0) ? g_qh : (z == 1) ? g_kh : g_vh;
    __nv_bfloat16* __restrict__ outL = (z == 0) ? g_ql : (z == 1) ? g_kl : g_vl;
    const float scale = (z == 0) ? 0.125f : 1.0f;

    const int m0 = blockIdx.x * 128;
    const int n0 = blockIdx.y * 128;

    float d[2][8][4];
    gemm_core(Xh, Xl, Wh, Wl, m0, n0, uS, d);

    const int lane = threadIdx.x & 31, wid = threadIdx.x >> 5;
    const int g = lane >> 2, t = lane & 3;
    const int wm0 = (wid >> 1) * 32, wn0 = (wid & 1) * 64;

    #pragma unroll
    for (int mi = 0; mi < 2; mi++)
        #pragma unroll
        for (int ni = 0; ni < 8; ni++) {
            const int n = n0 + wn0 + ni * 8 + t * 2;
            const int h = n >> 6, d0 = n & 63;
            #pragma unroll
            for (int half = 0; half < 2; half++) {
                const int m = m0 + wm0 + mi * 16 + g + half * 8;
                const int b = m >> 11, s = m & (SS - 1);
                unsigned hi, lo;
                split2(d[mi][ni][half*2] * scale, d[mi][ni][half*2+1] * scale, hi, lo);
                const size_t idx = (((size_t)(b * HH + h) * SS) + s) * DKK + d0;
                *(unsigned*)&outH[idx] = hi;
                *(unsigned*)&outL[idx] = lo;
            }
        }
}

// ===========================================================================
// Output projection + bias. grid (32, 6), block 256.
// ===========================================================================
__global__ __launch_bounds__(256, 2) void tc_outproj_kernel(
    const float* __restrict__ bo, float* __restrict__ out)
{
    extern __shared__ char smem[];
    const unsigned uS = smem_u32(smem);
    const int m0 = blockIdx.x * 128;
    const int n0 = blockIdx.y * 128;

    float d[2][8][4];
    gemm_core(g_ah, g_al, g_hi + WOFF + 3 * WSZ, g_lo + WOFF + 3 * WSZ,
              m0, n0, uS, d);

    const int lane = threadIdx.x & 31, wid = threadIdx.x >> 5;
    const int g = lane >> 2, t = lane & 3;
    const int wm0 = (wid >> 1) * 32, wn0 = (wid & 1) * 64;

    #pragma unroll
    for (int mi = 0; mi < 2; mi++)
        #pragma unroll
        for (int ni = 0; ni < 8; ni++) {
            const int n = n0 + wn0 + ni * 8 + t * 2;
            const float b0v = bo[n], b1v = bo[n + 1];
            #pragma unroll
            for (int half = 0; half < 2; half++) {
                const int m = m0 + wm0 + mi * 16 + g + half * 8;
                *(float2*)&out[(size_t)m * DD + n] =
                    make_float2(d[mi][ni][half*2] + b0v, d[mi][ni][half*2+1] + b1v);
            }
        }
}

// ===========================================================================
// Flash attention (split-bf16 mma.sync, causal), 3-stage cp.async K/V pipeline.
// Stage 3 overlays the (dead after prologue) Q staging region:
//   stage(kt) = uS + ((kt+1)%3)*32KB ;  kt=2 lands on the Q buffer.
// grid (16, 24), block 256, 96KB smem, 2 CTA/SM. Single sync per iteration.
// ===========================================================================
#define ATTN_SMEM 98304

__device__ __forceinline__ void attn_issue(
    const __nv_bfloat16* __restrict__ Khg, const __nv_bfloat16* __restrict__ Klg,
    const __nv_bfloat16* __restrict__ Vhg, const __nv_bfloat16* __restrict__ Vlg,
    int kt, unsigned dst)
{
    const int tid = threadIdx.x;
    #pragma unroll
    for (int j = 0; j < 2; j++) {
        int u = tid + j * 256, r = u >> 3, o = u & 7;
        unsigned off = r * 128 + ((o ^ (r & 7)) * 16);
        size_t src = (size_t)(kt * 64 + r) * 64 + o * 8;
        cpa16(dst +         off, Khg + src);
        cpa16(dst +  8192 + off, Klg + src);
        cpa16(dst + 16384 + off, Vhg + src);
        cpa16(dst + 24576 + off, Vlg + src);
    }
}

__global__ __launch_bounds__(256, 2) void attn_mma_kernel()
{
    extern __shared__ char smem[];
    const unsigned uS = smem_u32(smem);
    const unsigned uQh = uS, uQl = uS + 16384;

    const int qt = (int)gridDim.x - 1 - blockIdx.x;   // big tiles first
    const int bh = blockIdx.y;
    const int tid = threadIdx.x, lane = tid & 31, wid = tid >> 5;
    const int l15 = lane & 15, lhi = lane >> 4, l7 = lane & 7;
    const int wm0 = wid * 16;

    const __nv_bfloat16* __restrict__ Qhg = g_qh + ((size_t)bh * SS + qt * 128) * DKK;
    const __nv_bfloat16* __restrict__ Qlg = g_ql + ((size_t)bh * SS + qt * 128) * DKK;
    const __nv_bfloat16* __restrict__ Khg = g_kh + (size_t)bh * SS * DKK;
    const __nv_bfloat16* __restrict__ Klg = g_kl + (size_t)bh * SS * DKK;
    const __nv_bfloat16* __restrict__ Vhg = g_vh + (size_t)bh * SS * DKK;
    const __nv_bfloat16* __restrict__ Vlg = g_vl + (size_t)bh * SS * DKK;

    const int niter = 2 * qt + 2;

    // prologue: start K/V pipeline into stages 1,2; load Q into stage-0 region
    attn_issue(Khg, Klg, Vhg, Vlg, 0, uS + 32768);  CP_COMMIT();
    attn_issue(Khg, Klg, Vhg, Vlg, 1, uS + 65536);  CP_COMMIT();

    #pragma unroll
    for (int i = 0; i < 4; i++) {
        int u = i * 256 + tid;
        int r = u >> 3, o = u & 7;
        int off = r * 128 + ((o ^ (r & 7)) * 16);
        *(uint4*)(smem + off)         = *(const uint4*)(Qhg + r * 64 + o * 8);
        *(uint4*)(smem + 16384 + off) = *(const uint4*)(Qlg + r * 64 + o * 8);
    }
    __syncthreads();

    unsigned qh[4][4], ql[4][4];
    #pragma unroll
    for (int ks = 0; ks < 4; ks++) {
        const int sw = (((2 * ks + lhi) ^ l7) * 16);
        ldm_x4(qh[ks], uQh + (wm0 + l15) * 128 + sw);
        ldm_x4(ql[ks], uQl + (wm0 + l15) * 128 + sw);
    }

    float o_[8][4];
    #pragma unroll
    for (int t2 = 0; t2 < 8; t2++)
        #pragma unroll
        for (int k = 0; k < 4; k++) o_[t2][k] = 0.0f;
    float m0 = -1e30f, m1 = -1e30f, l0 = 0.0f, l1 = 0.0f;

    for (int kt = 0; kt < niter; kt++) {
        if (kt + 1 < niter) CP_WAIT1(); else CP_WAIT0();
        __syncthreads();   // all warps done with tile kt-1 (and Q extraction)
        if (kt + 2 < niter) {
            attn_issue(Khg, Klg, Vhg, Vlg, kt + 2, uS + ((kt + 3) % 3) * 32768);
            CP_COMMIT();
        }
        const unsigned kb = uS + ((kt + 1) % 3) * 32768;
        const unsigned uKh = kb, uKl = kb + 8192, uVh = kb + 16384, uVl = kb + 24576;

        const bool active = !(kt == 2 * qt + 1 && wid < 4);
        if (active) {
            // ---- S = Q K^T (3 split products) ----
            float s[8][4];
            #pragma unroll
            for (int t2 = 0; t2 < 8; t2++)
                #pragma unroll
                for (int k = 0; k < 4; k++) s[t2][k] = 0.0f;

            #pragma unroll
            for (int ks = 0; ks < 4; ks++) {
                const int sw = (((2 * ks + lhi) ^ l7) * 16);
                #pragma unroll
                for (int np = 0; np < 4; np++) {
                    unsigned bh_[4], bl_[4];
                    ldm_x4(bh_, uKh + (np * 16 + l15) * 128 + sw);
                    ldm_x4(bl_, uKl + (np * 16 + l15) * 128 + sw);
                    mma_bf16(s[2*np],   qh[ks], bh_[0], bh_[2]);
                    mma_bf16(s[2*np+1], qh[ks], bh_[1], bh_[3]);
                    mma_bf16(s[2*np],   qh[ks], bl_[0], bl_[2]);
                    mma_bf16(s[2*np+1], qh[ks], bl_[1], bl_[3]);
                    mma_bf16(s[2*np],   ql[ks], bh_[0], bh_[2]);
                    mma_bf16(s[2*np+1], ql[ks], bh_[1], bh_[3]);
                }
            }

            // ---- causal mask near diagonal ----
            if (kt >= 2 * qt) {
                const int row0 = qt * 128 + wm0 + (lane >> 2);
                const int colb = kt * 64 + 2 * (lane & 3);
                #pragma unroll
                for (int t2 = 0; t2 < 8; t2++) {
                    const int c0 = colb + t2 * 8;
                    if (c0     > row0)     s[t2][0] = -1e30f;
                    if (c0 + 1 > row0)     s[t2][1] = -1e30f;
                    if (c0     > row0 + 8) s[t2][2] = -1e30f;
                    if (c0 + 1 > row0 + 8) s[t2][3] = -1e30f;
                }
            }

            // ---- online softmax ----
            float mx0 = -1e30f, mx1 = -1e30f;
            #pragma unroll
            for (int t2 = 0; t2 < 8; t2++) {
                mx0 = fmaxf(mx0, fmaxf(s[t2][0], s[t2][1]));
                mx1 = fmaxf(mx1, fmaxf(s[t2][2], s[t2][3]));
            }
            mx0 = fmaxf(mx0, __shfl_xor_sync(0xffffffffu, mx0, 1));
            mx0 = fmaxf(mx0, __shfl_xor_sync(0xffffffffu, mx0, 2));
            mx1 = fmaxf(mx1, __shfl_xor_sync(0xffffffffu, mx1, 1));
            mx1 = fmaxf(mx1, __shfl_xor_sync(0xffffffffu, mx1, 2));
            const float mn0 = fmaxf(m0, mx0), mn1 = fmaxf(m1, mx1);
            const float a0 = __expf(m0 - mn0), a1 = __expf(m1 - mn1);
            m0 = mn0; m1 = mn1;

            float sum0 = 0.0f, sum1 = 0.0f;
            #pragma unroll
            for (int t2 = 0; t2 < 8; t2++) {
                s[t2][0] = __expf(s[t2][0] - mn0);
                s[t2][1] = __expf(s[t2][1] - mn0);
                s[t2][2] = __expf(s[t2][2] - mn1);
                s[t2][3] = __expf(s[t2][3] - mn1);
                sum0 += s[t2][0] + s[t2][1];
                sum1 += s[t2][2] + s[t2][3];
            }
            sum0 += __shfl_xor_sync(0xffffffffu, sum0, 1);
            sum0 += __shfl_xor_sync(0xffffffffu, sum0, 2);
            sum1 += __shfl_xor_sync(0xffffffffu, sum1, 1);
            sum1 += __shfl_xor_sync(0xffffffffu, sum1, 2);
            l0 = l0 * a0 + sum0;
            l1 = l1 * a1 + sum1;

            #pragma unroll
            for (int t2 = 0; t2 < 8; t2++) {
                o_[t2][0] *= a0; o_[t2][1] *= a0;
                o_[t2][2] *= a1; o_[t2][3] *= a1;
            }

            // ---- O += P V (3 split products) ----
            #pragma unroll
            for (int ks = 0; ks < 4; ks++) {
                unsigned ph[4], pl[4];
                split2(s[2*ks][0],   s[2*ks][1],   ph[0], pl[0]);
                split2(s[2*ks][2],   s[2*ks][3],   ph[1], pl[1]);
                split2(s[2*ks+1][0], s[2*ks+1][1], ph[2], pl[2]);
                split2(s[2*ks+1][2], s[2*ks+1][3], ph[3], pl[3]);
                #pragma unroll
                for (int dp = 0; dp < 4; dp++) {
                    unsigned vh[4], vl[4];
                    const int sw = (((2 * dp + lhi) ^ l7) * 16);
                    ldm_x4_t(vh, uVh + (ks * 16 + l15) * 128 + sw);
                    ldm_x4_t(vl, uVl + (ks * 16 + l15) * 128 + sw);
                    mma_bf16(o_[2*dp],   ph, vh[0], vh[1]);
                    mma_bf16(o_[2*dp+1], ph, vh[2], vh[3]);
                    mma_bf16(o_[2*dp],   ph, vl[0], vl[1]);
                    mma_bf16(o_[2*dp+1], ph, vl[2], vl[3]);
                    mma_bf16(o_[2*dp],   pl, vh[0], vh[1]);
                    mma_bf16(o_[2*dp+1], pl, vh[2], vh[3]);
                }
            }
        }
    }

    // ---- epilogue: normalize, write attended split-bf16 [B*S, D] ----
    const float inv0 = 1.0f / l0, inv1 = 1.0f / l1;
    const int b = bh / HH, h = bh - b * HH;
    const int row0 = qt * 128 + wm0 + (lane >> 2);
    #pragma unroll
    for (int t2 = 0; t2 < 8; t2++) {
        const int col = h * 64 + t2 * 8 + 2 * (lane & 3);
        unsigned hi, lo;
        split2(o_[t2][0] * inv0, o_[t2][1] * inv0, hi, lo);
        size_t i0 = ((size_t)(b * SS + row0)) * DD + col;
        *(unsigned*)&g_ah[i0] = hi;
        *(unsigned*)&g_al[i0] = lo;
        split2(o_[t2][2] * inv1, o_[t2][3] * inv1, hi, lo);
        size_t i1 = ((size_t)(b * SS + row0 + 8)) * DD + col;
        *(unsigned*)&g_ah[i1] = hi;
        *(unsigned*)&g_al[i1] = lo;
    }
}

// ===========================================================================
extern "C" void kernel_launch(void* const* d_in, const int* in_sizes, int n_in,
                              void* d_out, int out_size)
{
    const float* query = (const float*)d_in[0];
    const float* key   = (const float*)d_in[1];
    const float* value = (const float*)d_in[2];
    // d_in[3] = mask (fixed causal triu, handled analytically)
    const float* wq = (const float*)d_in[4];
    const float* wk = (const float*)d_in[5];
    const float* wv = (const float*)d_in[6];
    const float* wo = (const float*)d_in[7];
    const float* bo = (const float*)d_in[8];
    float* out = (float*)d_out;

    cudaFuncSetAttribute(tc_proj_kernel, cudaFuncAttributeMaxDynamicSharedMemorySize, GEMM_SMEM);
    cudaFuncSetAttribute(tc_outproj_kernel, cudaFuncAttributeMaxDynamicSharedMemorySize, GEMM_SMEM);
    cudaFuncSetAttribute(attn_mma_kernel, cudaFuncAttributeMaxDynamicSharedMemorySize, ATTN_SMEM);

    split_pass<<<dim3((int)(XSZ/8/256), 7), 256>>>(query, key, value, wq, wk, wv, wo);
    tc_proj_kernel<<<dim3(MM/128, DD/128, 3), 256, GEMM_SMEM>>>();
    attn_mma_kernel<<<dim3(SS/128, BB*HH), 256, ATTN_SMEM>>>();
    tc_outproj_kernel<<<dim3(MM/128, DD/128), 256, GEMM_SMEM>>>(bo, out);
}